// round 8
// baseline (speedup 1.0000x reference)
#include <cuda_runtime.h>
#include <cuda_bf16.h>
#include <mma.h>
#include <cstdint>
#include <cstddef>

using namespace nvcuda;

#define BATCH 4
#define SEQ   2048
#define CH    1024

// GEMM tiling (R4-proven): CTA 128x128, 8 warps (4m x 2n), warp 32x64
#define BKC 32                       // k per stage
#define BKP 40                       // padded smem ld (elems)
#define ARR_BYTES (128 * BKP * 2)    // one operand array: 10240 B
#define STAGE_BYTES (4 * ARR_BYTES)  // Ah, Al, Bh, Bl: 40960 B
#define NSTAGE 3
#define GEMM_SMEM (NSTAGE * STAGE_BYTES)   // 122880 B

// ---------------------------------------------------------------------------
// helpers
// ---------------------------------------------------------------------------
__device__ __forceinline__ uint32_t smem_u32(const void* p) {
    uint32_t a;
    asm("{ .reg .u64 t; cvta.to.shared.u64 t, %1; cvt.u32.u64 %0, t; }"
        : "=r"(a) : "l"(p));
    return a;
}

__device__ __forceinline__ void cp_async16(void* dst, const void* src) {
    uint32_t d = smem_u32(dst);
    asm volatile("cp.async.cg.shared.global [%0], [%1], 16;"
                 :: "r"(d), "l"(src) : "memory");
}
__device__ __forceinline__ void cp_commit() {
    asm volatile("cp.async.commit_group;" ::: "memory");
}
template <int N>
__device__ __forceinline__ void cp_wait_group() {
    asm volatile("cp.async.wait_group %0;" :: "n"(N) : "memory");
}

// fp32 pair -> hi/lo bf16x2 words
__device__ __forceinline__ void split2(float a, float b, uint32_t& hi, uint32_t& lo) {
    __nv_bfloat16 ha = __float2bfloat16(a);
    __nv_bfloat16 hb = __float2bfloat16(b);
    __nv_bfloat16 la = __float2bfloat16(a - __bfloat162float(ha));
    __nv_bfloat16 lb = __float2bfloat16(b - __bfloat162float(hb));
    hi = (uint32_t)__bfloat16_as_ushort(ha) | ((uint32_t)__bfloat16_as_ushort(hb) << 16);
    lo = (uint32_t)__bfloat16_as_ushort(la) | ((uint32_t)__bfloat16_as_ushort(lb) << 16);
}

// ---------------------------------------------------------------------------
// scratch (row-major everywhere)
// ---------------------------------------------------------------------------
#define NXE ((size_t)BATCH * SEQ * CH)
#define NWE ((size_t)CH * CH)
#define NSE ((size_t)BATCH * SEQ * SEQ)

__device__ __align__(1024) __nv_bfloat16 g_xqh[NXE], g_xql[NXE];
__device__ __align__(1024) __nv_bfloat16 g_xkh[NXE], g_xkl[NXE];
__device__ __align__(1024) __nv_bfloat16 g_xvh[NXE], g_xvl[NXE];
__device__ __align__(1024) __nv_bfloat16 g_wqh[NWE], g_wql[NWE];
__device__ __align__(1024) __nv_bfloat16 g_wkh[NWE], g_wkl[NWE];
__device__ __align__(1024) __nv_bfloat16 g_wvh[NWE], g_wvl[NWE];
__device__ __align__(1024) __nv_bfloat16 g_Qh[NXE],  g_Ql[NXE];
__device__ __align__(1024) __nv_bfloat16 g_Kh[NXE],  g_Kl[NXE];
__device__ __align__(1024) float         g_Vf[NXE];
__device__ __align__(1024) __nv_bfloat16 g_Vth[NXE], g_Vtl[NXE];
__device__ __align__(1024) float         g_Sf[NSE];
__device__ __align__(1024) __nv_bfloat16 g_Sh[NSE],  g_Sl[NSE];

// ---------------------------------------------------------------------------
// fused packing: all 3 inputs (4096 blocks each) + 3 weights (512 blocks each)
// ---------------------------------------------------------------------------
struct PackJob {
    const float* srcX;  __nv_bfloat16 *xh, *xl;
    const float* srcW;  __nv_bfloat16 *wh, *wl;
};

__global__ void __launch_bounds__(256)
pack_all(PackJob j0, PackJob j1, PackJob j2)
{
    const PackJob& j = (blockIdx.y == 0) ? j0 : (blockIdx.y == 1) ? j1 : j2;
    const float* src;
    __nv_bfloat16 *dh, *dl;
    size_t base;
    if (blockIdx.x < 4096) {
        src = j.srcX; dh = j.xh; dl = j.xl;
        base = ((size_t)blockIdx.x * 256 + threadIdx.x) * 8;
    } else {
        src = j.srcW; dh = j.wh; dl = j.wl;
        base = ((size_t)(blockIdx.x - 4096) * 256 + threadIdx.x) * 8;
    }
    float4 f0 = *reinterpret_cast<const float4*>(src + base);
    float4 f1 = *reinterpret_cast<const float4*>(src + base + 4);
    uint4 H, L;
    split2(f0.x, f0.y, H.x, L.x);
    split2(f0.z, f0.w, H.y, L.y);
    split2(f1.x, f1.y, H.z, L.z);
    split2(f1.z, f1.w, H.w, L.w);
    *reinterpret_cast<uint4*>((char*)dh + base * 2) = H;
    *reinterpret_cast<uint4*>((char*)dl + base * 2) = L;
}

// ---------------------------------------------------------------------------
// V fp32 [B][S][C] -> V^T hi/lo [B][C][S]
// ---------------------------------------------------------------------------
__global__ void __launch_bounds__(256)
transpose_pack(const float* __restrict__ V,
               __nv_bfloat16* __restrict__ Dh, __nv_bfloat16* __restrict__ Dl)
{
    __shared__ float sb[64 * 129];
    int kc = blockIdx.x, dBlk = blockIdx.y, b = blockIdx.z;
    int seq0 = kc * 64, d0 = dBlk * 128;
    int t = threadIdx.x;
#pragma unroll
    for (int i = 0; i < 8; i++) {
        int idx = t + i * 256;
        int s = idx >> 5, d4 = (idx & 31) * 4;
        float4 v = *reinterpret_cast<const float4*>(
            V + ((size_t)b * SEQ + seq0 + s) * CH + d0 + d4);
        sb[s * 129 + d4 + 0] = v.x;
        sb[s * 129 + d4 + 1] = v.y;
        sb[s * 129 + d4 + 2] = v.z;
        sb[s * 129 + d4 + 3] = v.w;
    }
    __syncthreads();
#pragma unroll
    for (int i = 0; i < 4; i++) {
        int idx = t + i * 256;
        int d = idx >> 3, s8 = (idx & 7) * 8;
        uint4 H, L;
        float v0 = sb[(s8 + 0) * 129 + d], v1 = sb[(s8 + 1) * 129 + d];
        float v2 = sb[(s8 + 2) * 129 + d], v3 = sb[(s8 + 3) * 129 + d];
        float v4 = sb[(s8 + 4) * 129 + d], v5 = sb[(s8 + 5) * 129 + d];
        float v6 = sb[(s8 + 6) * 129 + d], v7 = sb[(s8 + 7) * 129 + d];
        split2(v0, v1, H.x, L.x);
        split2(v2, v3, H.y, L.y);
        split2(v4, v5, H.z, L.z);
        split2(v6, v7, H.w, L.w);
        size_t e = ((size_t)b * CH + d0 + d) * SEQ + seq0 + s8;
        *reinterpret_cast<uint4*>((char*)Dh + e * 2) = H;
        *reinterpret_cast<uint4*>((char*)Dl + e * 2) = L;
    }
}

// ---------------------------------------------------------------------------
// softmax over rows of S fp32 [B*S][2048] -> hi/lo bf16 row-major
// ---------------------------------------------------------------------------
__global__ void __launch_bounds__(256)
softmax_pack(const float* __restrict__ S,
             __nv_bfloat16* __restrict__ Dh, __nv_bfloat16* __restrict__ Dl)
{
    __shared__ float red[32];
    int rowG = blockIdx.x, t = threadIdx.x;
    const float* row = S + (size_t)rowG * SEQ;
    float4 a = *reinterpret_cast<const float4*>(row + t * 8);
    float4 b2 = *reinterpret_cast<const float4*>(row + t * 8 + 4);
    float v[8] = {a.x, a.y, a.z, a.w, b2.x, b2.y, b2.z, b2.w};

    float m = v[0];
#pragma unroll
    for (int i = 1; i < 8; i++) m = fmaxf(m, v[i]);
#pragma unroll
    for (int o = 16; o > 0; o >>= 1)
        m = fmaxf(m, __shfl_xor_sync(0xffffffffu, m, o));
    if ((t & 31) == 0) red[t >> 5] = m;
    __syncthreads();
    if (t < 32) {
        float x = (t < 8) ? red[t] : -3.4e38f;
#pragma unroll
        for (int o = 4; o > 0; o >>= 1) x = fmaxf(x, __shfl_xor_sync(0xffffffffu, x, o));
        if (t == 0) red[0] = x;
    }
    __syncthreads();
    m = red[0];
    __syncthreads();

    float sum = 0.0f;
#pragma unroll
    for (int i = 0; i < 8; i++) { v[i] = __expf(v[i] - m); sum += v[i]; }
#pragma unroll
    for (int o = 16; o > 0; o >>= 1) sum += __shfl_xor_sync(0xffffffffu, sum, o);
    if ((t & 31) == 0) red[t >> 5] = sum;
    __syncthreads();
    if (t < 32) {
        float x = (t < 8) ? red[t] : 0.0f;
#pragma unroll
        for (int o = 4; o > 0; o >>= 1) x += __shfl_xor_sync(0xffffffffu, x, o);
        if (t == 0) red[0] = x;
    }
    __syncthreads();
    float inv = 1.0f / red[0];

    uint4 H, L;
    split2(v[0] * inv, v[1] * inv, H.x, L.x);
    split2(v[2] * inv, v[3] * inv, H.y, L.y);
    split2(v[4] * inv, v[5] * inv, H.z, L.z);
    split2(v[6] * inv, v[7] * inv, H.w, L.w);
    size_t e = (size_t)rowG * SEQ + t * 8;
    *reinterpret_cast<uint4*>((char*)Dh + e * 2) = H;
    *reinterpret_cast<uint4*>((char*)Dl + e * 2) = L;
}

// ---------------------------------------------------------------------------
// WMMA bf16 hi/lo-split NT GEMM (R4 mainloop + term-major MMA ordering):
//   C[m,n] = alpha * sum_k A[m,k]*B[n,k] (+ bias[n])
// ---------------------------------------------------------------------------
__global__ void __launch_bounds__(256, 1)
tc_gemm(const __nv_bfloat16* __restrict__ Ah, const __nv_bfloat16* __restrict__ Al,
        const __nv_bfloat16* __restrict__ Bh, const __nv_bfloat16* __restrict__ Bl,
        int K, size_t aStride, size_t bStride,
        const float* __restrict__ bias, float alpha,
        float* __restrict__ outF, int ldC, size_t cStride,
        __nv_bfloat16* __restrict__ outH, __nv_bfloat16* __restrict__ outL,
        int ldP, size_t pStride)
{
    extern __shared__ char smem[];
    const int tid = threadIdx.x;
    const int wid = tid >> 5;
    const int bx = blockIdx.x, by = blockIdx.y, bz = blockIdx.z;
    const int m0 = by * 128, n0 = bx * 128;

    const __nv_bfloat16* Ahb = Ah + (size_t)bz * aStride + (size_t)m0 * K;
    const __nv_bfloat16* Alb = Al + (size_t)bz * aStride + (size_t)m0 * K;
    const __nv_bfloat16* Bhb = Bh + (size_t)bz * bStride + (size_t)n0 * K;
    const __nv_bfloat16* Blb = Bl + (size_t)bz * bStride + (size_t)n0 * K;

    const int nK = K / BKC;

    auto load_stage = [&](int s, int c) {
        char* st = smem + s * STAGE_BYTES;
        const int k0 = c * BKC;
#pragma unroll
        for (int i = 0; i < 2; i++) {
            int job = tid + i * 256;          // 512 jobs: 128 rows x 4 segs
            int r = job >> 2;
            int seg = job & 3;
            size_t goff = (size_t)r * K + k0 + seg * 8;
            uint32_t soff = (uint32_t)r * (BKP * 2) + seg * 16;
            cp_async16(st + soff,                 Ahb + goff);
            cp_async16(st + ARR_BYTES + soff,     Alb + goff);
            cp_async16(st + 2 * ARR_BYTES + soff, Bhb + goff);
            cp_async16(st + 3 * ARR_BYTES + soff, Blb + goff);
        }
    };

    wmma::fragment<wmma::accumulator, 16, 16, 16, float> acc[2][4];
#pragma unroll
    for (int i = 0; i < 2; i++)
#pragma unroll
        for (int j = 0; j < 4; j++) wmma::fill_fragment(acc[i][j], 0.0f);

#pragma unroll
    for (int s = 0; s < NSTAGE; s++) { load_stage(s, s); cp_commit(); }

    const int wm = (wid & 3) * 32;
    const int wn = (wid >> 2) * 64;

    for (int c = 0; c < nK; c++) {
        cp_wait_group<NSTAGE - 1>();
        __syncthreads();

        const char* st = smem + (c % NSTAGE) * STAGE_BYTES;
        const __nv_bfloat16* As_h = (const __nv_bfloat16*)st;
        const __nv_bfloat16* As_l = As_h + 128 * BKP;
        const __nv_bfloat16* Bs_h = As_h + 2 * 128 * BKP;
        const __nv_bfloat16* Bs_l = As_h + 3 * 128 * BKP;

#pragma unroll
        for (int ks = 0; ks < 2; ks++) {
            wmma::fragment<wmma::matrix_a, 16, 16, 16, __nv_bfloat16, wmma::row_major> fah[2], fal[2];
            wmma::fragment<wmma::matrix_b, 16, 16, 16, __nv_bfloat16, wmma::col_major> fbh[4], fbl[4];
#pragma unroll
            for (int i = 0; i < 2; i++) {
                wmma::load_matrix_sync(fah[i], As_h + (wm + i * 16) * BKP + ks * 16, BKP);
                wmma::load_matrix_sync(fal[i], As_l + (wm + i * 16) * BKP + ks * 16, BKP);
            }
#pragma unroll
            for (int j = 0; j < 4; j++) {
                wmma::load_matrix_sync(fbh[j], Bs_h + (wn + j * 16) * BKP + ks * 16, BKP);
                wmma::load_matrix_sync(fbl[j], Bs_l + (wn + j * 16) * BKP + ks * 16, BKP);
            }
            // term-major: 8 independent MMAs per pass; each accumulator's
            // updates are 8 instructions apart (no RAW chain on HMMA latency)
#pragma unroll
            for (int i = 0; i < 2; i++)
#pragma unroll
                for (int j = 0; j < 4; j++)
                    wmma::mma_sync(acc[i][j], fah[i], fbh[j], acc[i][j]);
#pragma unroll
            for (int i = 0; i < 2; i++)
#pragma unroll
                for (int j = 0; j < 4; j++)
                    wmma::mma_sync(acc[i][j], fah[i], fbl[j], acc[i][j]);
#pragma unroll
            for (int i = 0; i < 2; i++)
#pragma unroll
                for (int j = 0; j < 4; j++)
                    wmma::mma_sync(acc[i][j], fal[i], fbh[j], acc[i][j]);
        }
        __syncthreads();
        if (c + NSTAGE < nK) load_stage(c % NSTAGE, c + NSTAGE);
        cp_commit();
    }
    cp_wait_group<0>();
    __syncthreads();

    // epilogue via smem staging
    float* Cs = (float*)smem;
#pragma unroll
    for (int i = 0; i < 2; i++)
#pragma unroll
        for (int j = 0; j < 4; j++)
            wmma::store_matrix_sync(Cs + (wm + i * 16) * 128 + wn + j * 16,
                                    acc[i][j], 128, wmma::mem_row_major);
    __syncthreads();

#pragma unroll
    for (int it = 0; it < 16; it++) {
        int g = tid + it * 256;               // 4096 float4 groups
        int r = g >> 5, c4 = (g & 31) * 4;
        float4 v = *reinterpret_cast<const float4*>(Cs + r * 128 + c4);
        float o0 = v.x * alpha, o1 = v.y * alpha;
        float o2 = v.z * alpha, o3 = v.w * alpha;
        if (bias) {
            o0 += bias[n0 + c4 + 0];
            o1 += bias[n0 + c4 + 1];
            o2 += bias[n0 + c4 + 2];
            o3 += bias[n0 + c4 + 3];
        }
        if (outF) {
            float4 w = {o0, o1, o2, o3};
            *reinterpret_cast<float4*>(outF + (size_t)bz * cStride
                + (size_t)(m0 + r) * ldC + n0 + c4) = w;
        }
        if (outH) {
            uint2 H, L;
            split2(o0, o1, H.x, L.x);
            split2(o2, o3, H.y, L.y);
            size_t e = (size_t)bz * pStride + (size_t)(m0 + r) * ldP + n0 + c4;
            *reinterpret_cast<uint2*>((char*)outH + e * 2) = H;
            *reinterpret_cast<uint2*>((char*)outL + e * 2) = L;
        }
    }
}

// ---------------------------------------------------------------------------
extern "C" void kernel_launch(void* const* d_in, const int* in_sizes, int n_in,
                              void* d_out, int out_size)
{
    const float* query = (const float*)d_in[0];
    const float* key   = (const float*)d_in[1];
    const float* value = (const float*)d_in[2];
    const float* Wq    = (const float*)d_in[3];
    const float* bq    = (const float*)d_in[4];
    const float* Wk    = (const float*)d_in[5];
    const float* bk    = (const float*)d_in[6];
    const float* Wv    = (const float*)d_in[7];
    const float* bv    = (const float*)d_in[8];
    float* out = (float*)d_out;

    cudaFuncSetAttribute(tc_gemm, cudaFuncAttributeMaxDynamicSharedMemorySize,
                         GEMM_SMEM);

    __nv_bfloat16 *xqh, *xql, *xkh, *xkl, *xvh, *xvl;
    __nv_bfloat16 *wqh, *wql, *wkh, *wkl, *wvh, *wvl;
    __nv_bfloat16 *Qh, *Ql, *Kh, *Kl, *Vth, *Vtl, *Sh, *Sl;
    float *Vf, *Sf;
    cudaGetSymbolAddress((void**)&xqh, g_xqh); cudaGetSymbolAddress((void**)&xql, g_xql);
    cudaGetSymbolAddress((void**)&xkh, g_xkh); cudaGetSymbolAddress((void**)&xkl, g_xkl);
    cudaGetSymbolAddress((void**)&xvh, g_xvh); cudaGetSymbolAddress((void**)&xvl, g_xvl);
    cudaGetSymbolAddress((void**)&wqh, g_wqh); cudaGetSymbolAddress((void**)&wql, g_wql);
    cudaGetSymbolAddress((void**)&wkh, g_wkh); cudaGetSymbolAddress((void**)&wkl, g_wkl);
    cudaGetSymbolAddress((void**)&wvh, g_wvh); cudaGetSymbolAddress((void**)&wvl, g_wvl);
    cudaGetSymbolAddress((void**)&Qh, g_Qh);   cudaGetSymbolAddress((void**)&Ql, g_Ql);
    cudaGetSymbolAddress((void**)&Kh, g_Kh);   cudaGetSymbolAddress((void**)&Kl, g_Kl);
    cudaGetSymbolAddress((void**)&Vf, g_Vf);
    cudaGetSymbolAddress((void**)&Vth, g_Vth); cudaGetSymbolAddress((void**)&Vtl, g_Vtl);
    cudaGetSymbolAddress((void**)&Sf, g_Sf);
    cudaGetSymbolAddress((void**)&Sh, g_Sh);   cudaGetSymbolAddress((void**)&Sl, g_Sl);

    // launch #1: fused packing of all inputs + weights
    PackJob jq = {query, xqh, xql, Wq, wqh, wql};
    PackJob jk = {key,   xkh, xkl, Wk, wkh, wkl};
    PackJob jv = {value, xvh, xvl, Wv, wvh, wvl};
    pack_all<<<dim3(4608, 3), 256>>>(jq, jk, jv);

    // launches #2-4: projections [8192,1024] x W^T + b
    dim3 gp(8, 64, 1);
    tc_gemm<<<gp, 256, GEMM_SMEM>>>(xqh, xql, wqh, wql, CH, 0, 0, bq, 1.0f,
                                    nullptr, 0, 0, Qh, Ql, CH, 0);
    tc_gemm<<<gp, 256, GEMM_SMEM>>>(xkh, xkl, wkh, wkl, CH, 0, 0, bk, 1.0f,
                                    nullptr, 0, 0, Kh, Kl, CH, 0);
    tc_gemm<<<gp, 256, GEMM_SMEM>>>(xvh, xvl, wvh, wvl, CH, 0, 0, bv, 1.0f,
                                    Vf, CH, 0, nullptr, nullptr, 0, 0);

    // launch #5: V -> V^T hi/lo
    transpose_pack<<<dim3(32, 8, 4), 256>>>(Vf, Vth, Vtl);

    // launch #6 (ncu capture target): scores = Q K^T / 32, per batch
    dim3 gs(16, 16, 4);
    tc_gemm<<<gs, 256, GEMM_SMEM>>>(Qh, Ql, Kh, Kl, CH,
                                    (size_t)SEQ * CH, (size_t)SEQ * CH,
                                    nullptr, 1.0f / 32.0f,
                                    Sf, SEQ, (size_t)SEQ * SEQ,
                                    nullptr, nullptr, 0, 0);

    // launch #7: softmax + repack attn
    softmax_pack<<<BATCH * SEQ, 256>>>(Sf, Sh, Sl);

    // launch #8: out = attn @ V, per batch
    dim3 go(8, 16, 4);
    tc_gemm<<<go, 256, GEMM_SMEM>>>(Sh, Sl, Vth, Vtl, SEQ,
                                    (size_t)SEQ * SEQ, (size_t)CH * SEQ,
                                    nullptr, 1.0f,
                                    out, CH, (size_t)SEQ * CH,
                                    nullptr, nullptr, 0, 0);
}

// round 9
// speedup vs baseline: 1.4796x; 1.4796x over previous
#include <cuda_runtime.h>
#include <cuda_bf16.h>
#include <mma.h>
#include <cstdint>
#include <cstddef>

using namespace nvcuda;

#define BATCH 4
#define SEQ   2048
#define CH    1024

// GEMM tiling: CTA 128x128, 16 warps (4m x 4n), warp 32x32, 512 threads
#define NTH 512
#define BKC 32                       // k per stage
#define BKP 40                       // padded smem ld (elems)
#define ARR_BYTES (128 * BKP * 2)    // one operand array: 10240 B
#define STAGE_BYTES (4 * ARR_BYTES)  // Ah, Al, Bh, Bl: 40960 B
#define NSTAGE 3
#define GEMM_SMEM (NSTAGE * STAGE_BYTES)   // 122880 B

// ---------------------------------------------------------------------------
// helpers
// ---------------------------------------------------------------------------
__device__ __forceinline__ uint32_t smem_u32(const void* p) {
    uint32_t a;
    asm("{ .reg .u64 t; cvta.to.shared.u64 t, %1; cvt.u32.u64 %0, t; }"
        : "=r"(a) : "l"(p));
    return a;
}

__device__ __forceinline__ void cp_async16(void* dst, const void* src) {
    uint32_t d = smem_u32(dst);
    asm volatile("cp.async.cg.shared.global [%0], [%1], 16;"
                 :: "r"(d), "l"(src) : "memory");
}
__device__ __forceinline__ void cp_commit() {
    asm volatile("cp.async.commit_group;" ::: "memory");
}
template <int N>
__device__ __forceinline__ void cp_wait_group() {
    asm volatile("cp.async.wait_group %0;" :: "n"(N) : "memory");
}

// fp32 pair -> hi/lo bf16x2 words
__device__ __forceinline__ void split2(float a, float b, uint32_t& hi, uint32_t& lo) {
    __nv_bfloat16 ha = __float2bfloat16(a);
    __nv_bfloat16 hb = __float2bfloat16(b);
    __nv_bfloat16 la = __float2bfloat16(a - __bfloat162float(ha));
    __nv_bfloat16 lb = __float2bfloat16(b - __bfloat162float(hb));
    hi = (uint32_t)__bfloat16_as_ushort(ha) | ((uint32_t)__bfloat16_as_ushort(hb) << 16);
    lo = (uint32_t)__bfloat16_as_ushort(la) | ((uint32_t)__bfloat16_as_ushort(lb) << 16);
}

// ---------------------------------------------------------------------------
// scratch (row-major everywhere)
// ---------------------------------------------------------------------------
#define NXE ((size_t)BATCH * SEQ * CH)
#define NWE ((size_t)CH * CH)
#define NSE ((size_t)BATCH * SEQ * SEQ)

__device__ __align__(1024) __nv_bfloat16 g_xqh[NXE], g_xql[NXE];
__device__ __align__(1024) __nv_bfloat16 g_xkh[NXE], g_xkl[NXE];
__device__ __align__(1024) __nv_bfloat16 g_xvh[NXE], g_xvl[NXE];
__device__ __align__(1024) __nv_bfloat16 g_wqh[NWE], g_wql[NWE];
__device__ __align__(1024) __nv_bfloat16 g_wkh[NWE], g_wkl[NWE];
__device__ __align__(1024) __nv_bfloat16 g_wvh[NWE], g_wvl[NWE];
__device__ __align__(1024) __nv_bfloat16 g_Qh[NXE],  g_Ql[NXE];
__device__ __align__(1024) __nv_bfloat16 g_Kh[NXE],  g_Kl[NXE];
__device__ __align__(1024) float         g_Vf[NXE];
__device__ __align__(1024) __nv_bfloat16 g_Vth[NXE], g_Vtl[NXE];
__device__ __align__(1024) float         g_Sf[NSE];
__device__ __align__(1024) __nv_bfloat16 g_Sh[NSE],  g_Sl[NSE];

// ---------------------------------------------------------------------------
// fused packing: all 3 inputs (4096 blocks each) + 3 weights (512 blocks each)
// ---------------------------------------------------------------------------
struct PackJob {
    const float* srcX;  __nv_bfloat16 *xh, *xl;
    const float* srcW;  __nv_bfloat16 *wh, *wl;
};

__global__ void __launch_bounds__(256)
pack_all(PackJob j0, PackJob j1, PackJob j2)
{
    const PackJob& j = (blockIdx.y == 0) ? j0 : (blockIdx.y == 1) ? j1 : j2;
    const float* src;
    __nv_bfloat16 *dh, *dl;
    size_t base;
    if (blockIdx.x < 4096) {
        src = j.srcX; dh = j.xh; dl = j.xl;
        base = ((size_t)blockIdx.x * 256 + threadIdx.x) * 8;
    } else {
        src = j.srcW; dh = j.wh; dl = j.wl;
        base = ((size_t)(blockIdx.x - 4096) * 256 + threadIdx.x) * 8;
    }
    float4 f0 = *reinterpret_cast<const float4*>(src + base);
    float4 f1 = *reinterpret_cast<const float4*>(src + base + 4);
    uint4 H, L;
    split2(f0.x, f0.y, H.x, L.x);
    split2(f0.z, f0.w, H.y, L.y);
    split2(f1.x, f1.y, H.z, L.z);
    split2(f1.z, f1.w, H.w, L.w);
    *reinterpret_cast<uint4*>((char*)dh + base * 2) = H;
    *reinterpret_cast<uint4*>((char*)dl + base * 2) = L;
}

// ---------------------------------------------------------------------------
// V fp32 [B][S][C] -> V^T hi/lo [B][C][S]
// ---------------------------------------------------------------------------
__global__ void __launch_bounds__(256)
transpose_pack(const float* __restrict__ V,
               __nv_bfloat16* __restrict__ Dh, __nv_bfloat16* __restrict__ Dl)
{
    __shared__ float sb[64 * 129];
    int kc = blockIdx.x, dBlk = blockIdx.y, b = blockIdx.z;
    int seq0 = kc * 64, d0 = dBlk * 128;
    int t = threadIdx.x;
#pragma unroll
    for (int i = 0; i < 8; i++) {
        int idx = t + i * 256;
        int s = idx >> 5, d4 = (idx & 31) * 4;
        float4 v = *reinterpret_cast<const float4*>(
            V + ((size_t)b * SEQ + seq0 + s) * CH + d0 + d4);
        sb[s * 129 + d4 + 0] = v.x;
        sb[s * 129 + d4 + 1] = v.y;
        sb[s * 129 + d4 + 2] = v.z;
        sb[s * 129 + d4 + 3] = v.w;
    }
    __syncthreads();
#pragma unroll
    for (int i = 0; i < 4; i++) {
        int idx = t + i * 256;
        int d = idx >> 3, s8 = (idx & 7) * 8;
        uint4 H, L;
        float v0 = sb[(s8 + 0) * 129 + d], v1 = sb[(s8 + 1) * 129 + d];
        float v2 = sb[(s8 + 2) * 129 + d], v3 = sb[(s8 + 3) * 129 + d];
        float v4 = sb[(s8 + 4) * 129 + d], v5 = sb[(s8 + 5) * 129 + d];
        float v6 = sb[(s8 + 6) * 129 + d], v7 = sb[(s8 + 7) * 129 + d];
        split2(v0, v1, H.x, L.x);
        split2(v2, v3, H.y, L.y);
        split2(v4, v5, H.z, L.z);
        split2(v6, v7, H.w, L.w);
        size_t e = ((size_t)b * CH + d0 + d) * SEQ + seq0 + s8;
        *reinterpret_cast<uint4*>((char*)Dh + e * 2) = H;
        *reinterpret_cast<uint4*>((char*)Dl + e * 2) = L;
    }
}

// ---------------------------------------------------------------------------
// softmax over rows of S fp32 [B*S][2048] -> hi/lo bf16 row-major
// ---------------------------------------------------------------------------
__global__ void __launch_bounds__(256)
softmax_pack(const float* __restrict__ S,
             __nv_bfloat16* __restrict__ Dh, __nv_bfloat16* __restrict__ Dl)
{
    __shared__ float red[32];
    int rowG = blockIdx.x, t = threadIdx.x;
    const float* row = S + (size_t)rowG * SEQ;
    float4 a = *reinterpret_cast<const float4*>(row + t * 8);
    float4 b2 = *reinterpret_cast<const float4*>(row + t * 8 + 4);
    float v[8] = {a.x, a.y, a.z, a.w, b2.x, b2.y, b2.z, b2.w};

    float m = v[0];
#pragma unroll
    for (int i = 1; i < 8; i++) m = fmaxf(m, v[i]);
#pragma unroll
    for (int o = 16; o > 0; o >>= 1)
        m = fmaxf(m, __shfl_xor_sync(0xffffffffu, m, o));
    if ((t & 31) == 0) red[t >> 5] = m;
    __syncthreads();
    if (t < 32) {
        float x = (t < 8) ? red[t] : -3.4e38f;
#pragma unroll
        for (int o = 4; o > 0; o >>= 1) x = fmaxf(x, __shfl_xor_sync(0xffffffffu, x, o));
        if (t == 0) red[0] = x;
    }
    __syncthreads();
    m = red[0];
    __syncthreads();

    float sum = 0.0f;
#pragma unroll
    for (int i = 0; i < 8; i++) { v[i] = __expf(v[i] - m); sum += v[i]; }
#pragma unroll
    for (int o = 16; o > 0; o >>= 1) sum += __shfl_xor_sync(0xffffffffu, sum, o);
    if ((t & 31) == 0) red[t >> 5] = sum;
    __syncthreads();
    if (t < 32) {
        float x = (t < 8) ? red[t] : 0.0f;
#pragma unroll
        for (int o = 4; o > 0; o >>= 1) x += __shfl_xor_sync(0xffffffffu, x, o);
        if (t == 0) red[0] = x;
    }
    __syncthreads();
    float inv = 1.0f / red[0];

    uint4 H, L;
    split2(v[0] * inv, v[1] * inv, H.x, L.x);
    split2(v[2] * inv, v[3] * inv, H.y, L.y);
    split2(v[4] * inv, v[5] * inv, H.z, L.z);
    split2(v[6] * inv, v[7] * inv, H.w, L.w);
    size_t e = (size_t)rowG * SEQ + t * 8;
    *reinterpret_cast<uint4*>((char*)Dh + e * 2) = H;
    *reinterpret_cast<uint4*>((char*)Dl + e * 2) = L;
}

// ---------------------------------------------------------------------------
// WMMA bf16 hi/lo-split NT GEMM: C = alpha*A B^T (+bias)
// CTA 128x128, 16 warps (4m x 4n), warp 32x32, 512 threads.
// R4-proven mainloop: compute, then load next stage (NSTAGE=3).
// ---------------------------------------------------------------------------
__global__ void __launch_bounds__(NTH, 1)
tc_gemm(const __nv_bfloat16* __restrict__ Ah, const __nv_bfloat16* __restrict__ Al,
        const __nv_bfloat16* __restrict__ Bh, const __nv_bfloat16* __restrict__ Bl,
        int K, size_t aStride, size_t bStride,
        const float* __restrict__ bias, float alpha,
        float* __restrict__ outF, int ldC, size_t cStride,
        __nv_bfloat16* __restrict__ outH, __nv_bfloat16* __restrict__ outL,
        int ldP, size_t pStride)
{
    extern __shared__ char smem[];
    const int tid = threadIdx.x;
    const int wid = tid >> 5;
    const int bx = blockIdx.x, by = blockIdx.y, bz = blockIdx.z;
    const int m0 = by * 128, n0 = bx * 128;

    const __nv_bfloat16* Ahb = Ah + (size_t)bz * aStride + (size_t)m0 * K;
    const __nv_bfloat16* Alb = Al + (size_t)bz * aStride + (size_t)m0 * K;
    const __nv_bfloat16* Bhb = Bh + (size_t)bz * bStride + (size_t)n0 * K;
    const __nv_bfloat16* Blb = Bl + (size_t)bz * bStride + (size_t)n0 * K;

    const int nK = K / BKC;

    auto load_stage = [&](int s, int c) {
        char* st = smem + s * STAGE_BYTES;
        const int k0 = c * BKC;
        int r = tid >> 2;                     // 512 jobs: 128 rows x 4 segs
        int seg = tid & 3;
        size_t goff = (size_t)r * K + k0 + seg * 8;
        uint32_t soff = (uint32_t)r * (BKP * 2) + seg * 16;
        cp_async16(st + soff,                 Ahb + goff);
        cp_async16(st + ARR_BYTES + soff,     Alb + goff);
        cp_async16(st + 2 * ARR_BYTES + soff, Bhb + goff);
        cp_async16(st + 3 * ARR_BYTES + soff, Blb + goff);
    };

    wmma::fragment<wmma::accumulator, 16, 16, 16, float> acc[2][2];
#pragma unroll
    for (int i = 0; i < 2; i++)
#pragma unroll
        for (int j = 0; j < 2; j++) wmma::fill_fragment(acc[i][j], 0.0f);

#pragma unroll
    for (int s = 0; s < NSTAGE; s++) { load_stage(s, s); cp_commit(); }

    const int wm = (wid & 3) * 32;            // 4 m-warps
    const int wn = (wid >> 2) * 32;           // 4 n-warps

    for (int c = 0; c < nK; c++) {
        cp_wait_group<NSTAGE - 1>();
        __syncthreads();

        const char* st = smem + (c % NSTAGE) * STAGE_BYTES;
        const __nv_bfloat16* As_h = (const __nv_bfloat16*)st;
        const __nv_bfloat16* As_l = As_h + 128 * BKP;
        const __nv_bfloat16* Bs_h = As_h + 2 * 128 * BKP;
        const __nv_bfloat16* Bs_l = As_h + 3 * 128 * BKP;

#pragma unroll
        for (int ks = 0; ks < 2; ks++) {
            wmma::fragment<wmma::matrix_a, 16, 16, 16, __nv_bfloat16, wmma::row_major> fah[2], fal[2];
            wmma::fragment<wmma::matrix_b, 16, 16, 16, __nv_bfloat16, wmma::col_major> fbh[2], fbl[2];
#pragma unroll
            for (int i = 0; i < 2; i++) {
                wmma::load_matrix_sync(fah[i], As_h + (wm + i * 16) * BKP + ks * 16, BKP);
                wmma::load_matrix_sync(fal[i], As_l + (wm + i * 16) * BKP + ks * 16, BKP);
            }
#pragma unroll
            for (int j = 0; j < 2; j++) {
                wmma::load_matrix_sync(fbh[j], Bs_h + (wn + j * 16) * BKP + ks * 16, BKP);
                wmma::load_matrix_sync(fbl[j], Bs_l + (wn + j * 16) * BKP + ks * 16, BKP);
            }
#pragma unroll
            for (int i = 0; i < 2; i++)
#pragma unroll
                for (int j = 0; j < 2; j++) {
                    wmma::mma_sync(acc[i][j], fah[i], fbh[j], acc[i][j]);
                    wmma::mma_sync(acc[i][j], fah[i], fbl[j], acc[i][j]);
                    wmma::mma_sync(acc[i][j], fal[i], fbh[j], acc[i][j]);
                }
        }
        __syncthreads();
        if (c + NSTAGE < nK) load_stage(c % NSTAGE, c + NSTAGE);
        cp_commit();
    }
    cp_wait_group<0>();
    __syncthreads();

    // epilogue via smem staging (128x128 fp32 = 64KB)
    float* Cs = (float*)smem;
#pragma unroll
    for (int i = 0; i < 2; i++)
#pragma unroll
        for (int j = 0; j < 2; j++)
            wmma::store_matrix_sync(Cs + (wm + i * 16) * 128 + wn + j * 16,
                                    acc[i][j], 128, wmma::mem_row_major);
    __syncthreads();

#pragma unroll
    for (int it = 0; it < 8; it++) {
        int g = tid + it * NTH;               // 4096 float4 groups
        int r = g >> 5, c4 = (g & 31) * 4;
        float4 v = *reinterpret_cast<const float4*>(Cs + r * 128 + c4);
        float o0 = v.x * alpha, o1 = v.y * alpha;
        float o2 = v.z * alpha, o3 = v.w * alpha;
        if (bias) {
            o0 += bias[n0 + c4 + 0];
            o1 += bias[n0 + c4 + 1];
            o2 += bias[n0 + c4 + 2];
            o3 += bias[n0 + c4 + 3];
        }
        if (outF) {
            float4 w = {o0, o1, o2, o3};
            *reinterpret_cast<float4*>(outF + (size_t)bz * cStride
                + (size_t)(m0 + r) * ldC + n0 + c4) = w;
        }
        if (outH) {
            uint2 H, L;
            split2(o0, o1, H.x, L.x);
            split2(o2, o3, H.y, L.y);
            size_t e = (size_t)bz * pStride + (size_t)(m0 + r) * ldP + n0 + c4;
            *reinterpret_cast<uint2*>((char*)outH + e * 2) = H;
            *reinterpret_cast<uint2*>((char*)outL + e * 2) = L;
        }
    }
}

// ---------------------------------------------------------------------------
extern "C" void kernel_launch(void* const* d_in, const int* in_sizes, int n_in,
                              void* d_out, int out_size)
{
    const float* query = (const float*)d_in[0];
    const float* key   = (const float*)d_in[1];
    const float* value = (const float*)d_in[2];
    const float* Wq    = (const float*)d_in[3];
    const float* bq    = (const float*)d_in[4];
    const float* Wk    = (const float*)d_in[5];
    const float* bk    = (const float*)d_in[6];
    const float* Wv    = (const float*)d_in[7];
    const float* bv    = (const float*)d_in[8];
    float* out = (float*)d_out;

    cudaFuncSetAttribute(tc_gemm, cudaFuncAttributeMaxDynamicSharedMemorySize,
                         GEMM_SMEM);

    __nv_bfloat16 *xqh, *xql, *xkh, *xkl, *xvh, *xvl;
    __nv_bfloat16 *wqh, *wql, *wkh, *wkl, *wvh, *wvl;
    __nv_bfloat16 *Qh, *Ql, *Kh, *Kl, *Vth, *Vtl, *Sh, *Sl;
    float *Vf, *Sf;
    cudaGetSymbolAddress((void**)&xqh, g_xqh); cudaGetSymbolAddress((void**)&xql, g_xql);
    cudaGetSymbolAddress((void**)&xkh, g_xkh); cudaGetSymbolAddress((void**)&xkl, g_xkl);
    cudaGetSymbolAddress((void**)&xvh, g_xvh); cudaGetSymbolAddress((void**)&xvl, g_xvl);
    cudaGetSymbolAddress((void**)&wqh, g_wqh); cudaGetSymbolAddress((void**)&wql, g_wql);
    cudaGetSymbolAddress((void**)&wkh, g_wkh); cudaGetSymbolAddress((void**)&wkl, g_wkl);
    cudaGetSymbolAddress((void**)&wvh, g_wvh); cudaGetSymbolAddress((void**)&wvl, g_wvl);
    cudaGetSymbolAddress((void**)&Qh, g_Qh);   cudaGetSymbolAddress((void**)&Ql, g_Ql);
    cudaGetSymbolAddress((void**)&Kh, g_Kh);   cudaGetSymbolAddress((void**)&Kl, g_Kl);
    cudaGetSymbolAddress((void**)&Vf, g_Vf);
    cudaGetSymbolAddress((void**)&Vth, g_Vth); cudaGetSymbolAddress((void**)&Vtl, g_Vtl);
    cudaGetSymbolAddress((void**)&Sf, g_Sf);
    cudaGetSymbolAddress((void**)&Sh, g_Sh);   cudaGetSymbolAddress((void**)&Sl, g_Sl);

    // launch #1: fused packing of all inputs + weights
    PackJob jq = {query, xqh, xql, Wq, wqh, wql};
    PackJob jk = {key,   xkh, xkl, Wk, wkh, wkl};
    PackJob jv = {value, xvh, xvl, Wv, wvh, wvl};
    pack_all<<<dim3(4608, 3), 256>>>(jq, jk, jv);

    // launches #2-4: projections [8192,1024] x W^T + b
    dim3 gp(8, 64, 1);
    tc_gemm<<<gp, NTH, GEMM_SMEM>>>(xqh, xql, wqh, wql, CH, 0, 0, bq, 1.0f,
                                    nullptr, 0, 0, Qh, Ql, CH, 0);
    tc_gemm<<<gp, NTH, GEMM_SMEM>>>(xkh, xkl, wkh, wkl, CH, 0, 0, bk, 1.0f,
                                    nullptr, 0, 0, Kh, Kl, CH, 0);
    tc_gemm<<<gp, NTH, GEMM_SMEM>>>(xvh, xvl, wvh, wvl, CH, 0, 0, bv, 1.0f,
                                    Vf, CH, 0, nullptr, nullptr, 0, 0);

    // launch #5: V -> V^T hi/lo
    transpose_pack<<<dim3(32, 8, 4), 256>>>(Vf, Vth, Vtl);

    // launch #6: scores = Q K^T / 32, per batch
    dim3 gs(16, 16, 4);
    tc_gemm<<<gs, NTH, GEMM_SMEM>>>(Qh, Ql, Kh, Kl, CH,
                                    (size_t)SEQ * CH, (size_t)SEQ * CH,
                                    nullptr, 1.0f / 32.0f,
                                    Sf, SEQ, (size_t)SEQ * SEQ,
                                    nullptr, nullptr, 0, 0);

    // launch #7: softmax + repack attn
    softmax_pack<<<BATCH * SEQ, 256>>>(Sf, Sh, Sl);

    // launch #8: out = attn @ V, per batch
    dim3 go(8, 16, 4);
    tc_gemm<<<go, NTH, GEMM_SMEM>>>(Sh, Sl, Vth, Vtl, SEQ,
                                    (size_t)SEQ * SEQ, (size_t)CH * SEQ,
                                    nullptr, 1.0f,
                                    out, CH, (size_t)SEQ * CH,
                                    nullptr, nullptr, 0, 0);
}

// round 10
// speedup vs baseline: 1.7658x; 1.1934x over previous
#include <cuda_runtime.h>
#include <cuda_bf16.h>
#include <mma.h>
#include <cstdint>
#include <cstddef>

using namespace nvcuda;

#define BATCH 4
#define SEQ   2048
#define CH    1024

// GEMM tiling: CTA 64x128, 8 warps (2m x 4n), warp 32x32, 256 threads,
// 2 CTAs/SM (desynchronized phases).
#define NTH 256
#define BKC 32                        // k per stage
#define BKP 40                        // padded smem ld (elems) -> 80B rows
#define A_BYTES (64 * BKP * 2)        // 5120 B per A array
#define B_BYTES (128 * BKP * 2)       // 10240 B per B array
#define STAGE_BYTES (2 * A_BYTES + 2 * B_BYTES)   // 30720 B
#define NSTAGE 3
#define GEMM_SMEM (NSTAGE * STAGE_BYTES)          // 92160 B (x2 CTAs = 184320)

// ---------------------------------------------------------------------------
// helpers
// ---------------------------------------------------------------------------
__device__ __forceinline__ uint32_t smem_u32(const void* p) {
    uint32_t a;
    asm("{ .reg .u64 t; cvta.to.shared.u64 t, %1; cvt.u32.u64 %0, t; }"
        : "=r"(a) : "l"(p));
    return a;
}

__device__ __forceinline__ void cp_async16(void* dst, const void* src) {
    uint32_t d = smem_u32(dst);
    asm volatile("cp.async.cg.shared.global [%0], [%1], 16;"
                 :: "r"(d), "l"(src) : "memory");
}
__device__ __forceinline__ void cp_commit() {
    asm volatile("cp.async.commit_group;" ::: "memory");
}
template <int N>
__device__ __forceinline__ void cp_wait_group() {
    asm volatile("cp.async.wait_group %0;" :: "n"(N) : "memory");
}

// fp32 pair -> hi/lo bf16x2 words
__device__ __forceinline__ void split2(float a, float b, uint32_t& hi, uint32_t& lo) {
    __nv_bfloat16 ha = __float2bfloat16(a);
    __nv_bfloat16 hb = __float2bfloat16(b);
    __nv_bfloat16 la = __float2bfloat16(a - __bfloat162float(ha));
    __nv_bfloat16 lb = __float2bfloat16(b - __bfloat162float(hb));
    hi = (uint32_t)__bfloat16_as_ushort(ha) | ((uint32_t)__bfloat16_as_ushort(hb) << 16);
    lo = (uint32_t)__bfloat16_as_ushort(la) | ((uint32_t)__bfloat16_as_ushort(lb) << 16);
}

// ---------------------------------------------------------------------------
// scratch (row-major everywhere)
// ---------------------------------------------------------------------------
#define NXE ((size_t)BATCH * SEQ * CH)
#define NWE ((size_t)CH * CH)
#define NSE ((size_t)BATCH * SEQ * SEQ)

__device__ __align__(1024) __nv_bfloat16 g_xqh[NXE], g_xql[NXE];
__device__ __align__(1024) __nv_bfloat16 g_xkh[NXE], g_xkl[NXE];
__device__ __align__(1024) __nv_bfloat16 g_xvh[NXE], g_xvl[NXE];
__device__ __align__(1024) __nv_bfloat16 g_wqh[NWE], g_wql[NWE];
__device__ __align__(1024) __nv_bfloat16 g_wkh[NWE], g_wkl[NWE];
__device__ __align__(1024) __nv_bfloat16 g_wvh[NWE], g_wvl[NWE];
__device__ __align__(1024) __nv_bfloat16 g_Qh[NXE],  g_Ql[NXE];
__device__ __align__(1024) __nv_bfloat16 g_Kh[NXE],  g_Kl[NXE];
__device__ __align__(1024) float         g_Vf[NXE];
__device__ __align__(1024) __nv_bfloat16 g_Vth[NXE], g_Vtl[NXE];
__device__ __align__(1024) float         g_Sf[NSE];
__device__ __align__(1024) __nv_bfloat16 g_Sh[NSE],  g_Sl[NSE];

// ---------------------------------------------------------------------------
// fused packing: all 3 inputs (4096 blocks each) + 3 weights (512 blocks each)
// ---------------------------------------------------------------------------
struct PackJob {
    const float* srcX;  __nv_bfloat16 *xh, *xl;
    const float* srcW;  __nv_bfloat16 *wh, *wl;
};

__global__ void __launch_bounds__(256)
pack_all(PackJob j0, PackJob j1, PackJob j2)
{
    const PackJob& j = (blockIdx.y == 0) ? j0 : (blockIdx.y == 1) ? j1 : j2;
    const float* src;
    __nv_bfloat16 *dh, *dl;
    size_t base;
    if (blockIdx.x < 4096) {
        src = j.srcX; dh = j.xh; dl = j.xl;
        base = ((size_t)blockIdx.x * 256 + threadIdx.x) * 8;
    } else {
        src = j.srcW; dh = j.wh; dl = j.wl;
        base = ((size_t)(blockIdx.x - 4096) * 256 + threadIdx.x) * 8;
    }
    float4 f0 = *reinterpret_cast<const float4*>(src + base);
    float4 f1 = *reinterpret_cast<const float4*>(src + base + 4);
    uint4 H, L;
    split2(f0.x, f0.y, H.x, L.x);
    split2(f0.z, f0.w, H.y, L.y);
    split2(f1.x, f1.y, H.z, L.z);
    split2(f1.z, f1.w, H.w, L.w);
    *reinterpret_cast<uint4*>((char*)dh + base * 2) = H;
    *reinterpret_cast<uint4*>((char*)dl + base * 2) = L;
}

// ---------------------------------------------------------------------------
// V fp32 [B][S][C] -> V^T hi/lo [B][C][S]
// ---------------------------------------------------------------------------
__global__ void __launch_bounds__(256)
transpose_pack(const float* __restrict__ V,
               __nv_bfloat16* __restrict__ Dh, __nv_bfloat16* __restrict__ Dl)
{
    __shared__ float sb[64 * 129];
    int kc = blockIdx.x, dBlk = blockIdx.y, b = blockIdx.z;
    int seq0 = kc * 64, d0 = dBlk * 128;
    int t = threadIdx.x;
#pragma unroll
    for (int i = 0; i < 8; i++) {
        int idx = t + i * 256;
        int s = idx >> 5, d4 = (idx & 31) * 4;
        float4 v = *reinterpret_cast<const float4*>(
            V + ((size_t)b * SEQ + seq0 + s) * CH + d0 + d4);
        sb[s * 129 + d4 + 0] = v.x;
        sb[s * 129 + d4 + 1] = v.y;
        sb[s * 129 + d4 + 2] = v.z;
        sb[s * 129 + d4 + 3] = v.w;
    }
    __syncthreads();
#pragma unroll
    for (int i = 0; i < 4; i++) {
        int idx = t + i * 256;
        int d = idx >> 3, s8 = (idx & 7) * 8;
        uint4 H, L;
        float v0 = sb[(s8 + 0) * 129 + d], v1 = sb[(s8 + 1) * 129 + d];
        float v2 = sb[(s8 + 2) * 129 + d], v3 = sb[(s8 + 3) * 129 + d];
        float v4 = sb[(s8 + 4) * 129 + d], v5 = sb[(s8 + 5) * 129 + d];
        float v6 = sb[(s8 + 6) * 129 + d], v7 = sb[(s8 + 7) * 129 + d];
        split2(v0, v1, H.x, L.x);
        split2(v2, v3, H.y, L.y);
        split2(v4, v5, H.z, L.z);
        split2(v6, v7, H.w, L.w);
        size_t e = ((size_t)b * CH + d0 + d) * SEQ + seq0 + s8;
        *reinterpret_cast<uint4*>((char*)Dh + e * 2) = H;
        *reinterpret_cast<uint4*>((char*)Dl + e * 2) = L;
    }
}

// ---------------------------------------------------------------------------
// softmax over rows of S fp32 [B*S][2048] -> hi/lo bf16 row-major
// ---------------------------------------------------------------------------
__global__ void __launch_bounds__(256)
softmax_pack(const float* __restrict__ S,
             __nv_bfloat16* __restrict__ Dh, __nv_bfloat16* __restrict__ Dl)
{
    __shared__ float red[32];
    int rowG = blockIdx.x, t = threadIdx.x;
    const float* row = S + (size_t)rowG * SEQ;
    float4 a = *reinterpret_cast<const float4*>(row + t * 8);
    float4 b2 = *reinterpret_cast<const float4*>(row + t * 8 + 4);
    float v[8] = {a.x, a.y, a.z, a.w, b2.x, b2.y, b2.z, b2.w};

    float m = v[0];
#pragma unroll
    for (int i = 1; i < 8; i++) m = fmaxf(m, v[i]);
#pragma unroll
    for (int o = 16; o > 0; o >>= 1)
        m = fmaxf(m, __shfl_xor_sync(0xffffffffu, m, o));
    if ((t & 31) == 0) red[t >> 5] = m;
    __syncthreads();
    if (t < 32) {
        float x = (t < 8) ? red[t] : -3.4e38f;
#pragma unroll
        for (int o = 4; o > 0; o >>= 1) x = fmaxf(x, __shfl_xor_sync(0xffffffffu, x, o));
        if (t == 0) red[0] = x;
    }
    __syncthreads();
    m = red[0];
    __syncthreads();

    float sum = 0.0f;
#pragma unroll
    for (int i = 0; i < 8; i++) { v[i] = __expf(v[i] - m); sum += v[i]; }
#pragma unroll
    for (int o = 16; o > 0; o >>= 1) sum += __shfl_xor_sync(0xffffffffu, sum, o);
    if ((t & 31) == 0) red[t >> 5] = sum;
    __syncthreads();
    if (t < 32) {
        float x = (t < 8) ? red[t] : 0.0f;
#pragma unroll
        for (int o = 4; o > 0; o >>= 1) x += __shfl_xor_sync(0xffffffffu, x, o);
        if (t == 0) red[0] = x;
    }
    __syncthreads();
    float inv = 1.0f / red[0];

    uint4 H, L;
    split2(v[0] * inv, v[1] * inv, H.x, L.x);
    split2(v[2] * inv, v[3] * inv, H.y, L.y);
    split2(v[4] * inv, v[5] * inv, H.z, L.z);
    split2(v[6] * inv, v[7] * inv, H.w, L.w);
    size_t e = (size_t)rowG * SEQ + t * 8;
    *reinterpret_cast<uint4*>((char*)Dh + e * 2) = H;
    *reinterpret_cast<uint4*>((char*)Dl + e * 2) = L;
}

// ---------------------------------------------------------------------------
// WMMA bf16 hi/lo-split NT GEMM: C = alpha*A B^T (+bias)
// CTA 64x128, 8 warps (2m x 4n), warp 32x32, 2 CTAs/SM.
// ---------------------------------------------------------------------------
__global__ void __launch_bounds__(NTH, 2)
tc_gemm(const __nv_bfloat16* __restrict__ Ah, const __nv_bfloat16* __restrict__ Al,
        const __nv_bfloat16* __restrict__ Bh, const __nv_bfloat16* __restrict__ Bl,
        int K, size_t aStride, size_t bStride,
        const float* __restrict__ bias, float alpha,
        float* __restrict__ outF, int ldC, size_t cStride,
        __nv_bfloat16* __restrict__ outH, __nv_bfloat16* __restrict__ outL,
        int ldP, size_t pStride)
{
    extern __shared__ char smem[];
    const int tid = threadIdx.x;
    const int wid = tid >> 5;
    const int bx = blockIdx.x, by = blockIdx.y, bz = blockIdx.z;
    const int m0 = by * 64, n0 = bx * 128;

    const __nv_bfloat16* Ahb = Ah + (size_t)bz * aStride + (size_t)m0 * K;
    const __nv_bfloat16* Alb = Al + (size_t)bz * aStride + (size_t)m0 * K;
    const __nv_bfloat16* Bhb = Bh + (size_t)bz * bStride + (size_t)n0 * K;
    const __nv_bfloat16* Blb = Bl + (size_t)bz * bStride + (size_t)n0 * K;

    const int nK = K / BKC;

    // stage layout: [Ah 64xBKP][Al 64xBKP][Bh 128xBKP][Bl 128xBKP]
    auto load_stage = [&](int s, int c) {
        char* st = smem + s * STAGE_BYTES;
        const int k0 = c * BKC;
        {   // A: 256 jobs (64 rows x 4 segs), 1 per thread, 2 cp each
            int r = tid >> 2, seg = tid & 3;
            size_t goff = (size_t)r * K + k0 + seg * 8;
            uint32_t soff = (uint32_t)r * (BKP * 2) + seg * 16;
            cp_async16(st + soff,           Ahb + goff);
            cp_async16(st + A_BYTES + soff, Alb + goff);
        }
#pragma unroll
        for (int i = 0; i < 2; i++) {   // B: 512 jobs (128 rows x 4 segs)
            int job = tid + i * NTH;
            int r = job >> 2, seg = job & 3;
            size_t goff = (size_t)r * K + k0 + seg * 8;
            uint32_t soff = (uint32_t)r * (BKP * 2) + seg * 16;
            cp_async16(st + 2 * A_BYTES + soff,           Bhb + goff);
            cp_async16(st + 2 * A_BYTES + B_BYTES + soff, Blb + goff);
        }
    };

    wmma::fragment<wmma::accumulator, 16, 16, 16, float> acc[2][2];
#pragma unroll
    for (int i = 0; i < 2; i++)
#pragma unroll
        for (int j = 0; j < 2; j++) wmma::fill_fragment(acc[i][j], 0.0f);

#pragma unroll
    for (int s = 0; s < NSTAGE; s++) { load_stage(s, s); cp_commit(); }

    const int wm = (wid & 1) * 32;            // 2 m-warps
    const int wn = (wid >> 1) * 32;           // 4 n-warps

    for (int c = 0; c < nK; c++) {
        cp_wait_group<NSTAGE - 1>();
        __syncthreads();

        const char* st = smem + (c % NSTAGE) * STAGE_BYTES;
        const __nv_bfloat16* As_h = (const __nv_bfloat16*)st;
        const __nv_bfloat16* As_l = (const __nv_bfloat16*)(st + A_BYTES);
        const __nv_bfloat16* Bs_h = (const __nv_bfloat16*)(st + 2 * A_BYTES);
        const __nv_bfloat16* Bs_l = (const __nv_bfloat16*)(st + 2 * A_BYTES + B_BYTES);

#pragma unroll
        for (int ks = 0; ks < 2; ks++) {
            wmma::fragment<wmma::matrix_a, 16, 16, 16, __nv_bfloat16, wmma::row_major> fah[2], fal[2];
            wmma::fragment<wmma::matrix_b, 16, 16, 16, __nv_bfloat16, wmma::col_major> fbh[2], fbl[2];
#pragma unroll
            for (int i = 0; i < 2; i++) {
                wmma::load_matrix_sync(fah[i], As_h + (wm + i * 16) * BKP + ks * 16, BKP);
                wmma::load_matrix_sync(fal[i], As_l + (wm + i * 16) * BKP + ks * 16, BKP);
            }
#pragma unroll
            for (int j = 0; j < 2; j++) {
                wmma::load_matrix_sync(fbh[j], Bs_h + (wn + j * 16) * BKP + ks * 16, BKP);
                wmma::load_matrix_sync(fbl[j], Bs_l + (wn + j * 16) * BKP + ks * 16, BKP);
            }
#pragma unroll
            for (int i = 0; i < 2; i++)
#pragma unroll
                for (int j = 0; j < 2; j++) {
                    wmma::mma_sync(acc[i][j], fah[i], fbh[j], acc[i][j]);
                    wmma::mma_sync(acc[i][j], fah[i], fbl[j], acc[i][j]);
                    wmma::mma_sync(acc[i][j], fal[i], fbh[j], acc[i][j]);
                }
        }
        __syncthreads();
        if (c + NSTAGE < nK) load_stage(c % NSTAGE, c + NSTAGE);
        cp_commit();
    }
    cp_wait_group<0>();
    __syncthreads();

    // epilogue via smem staging (64x128 fp32 = 32KB, fits in 90KB stage mem)
    float* Cs = (float*)smem;
#pragma unroll
    for (int i = 0; i < 2; i++)
#pragma unroll
        for (int j = 0; j < 2; j++)
            wmma::store_matrix_sync(Cs + (wm + i * 16) * 128 + wn + j * 16,
                                    acc[i][j], 128, wmma::mem_row_major);
    __syncthreads();

#pragma unroll
    for (int it = 0; it < 8; it++) {
        int g = tid + it * NTH;               // 2048 float4 groups
        int r = g >> 5, c4 = (g & 31) * 4;
        float4 v = *reinterpret_cast<const float4*>(Cs + r * 128 + c4);
        float o0 = v.x * alpha, o1 = v.y * alpha;
        float o2 = v.z * alpha, o3 = v.w * alpha;
        if (bias) {
            o0 += bias[n0 + c4 + 0];
            o1 += bias[n0 + c4 + 1];
            o2 += bias[n0 + c4 + 2];
            o3 += bias[n0 + c4 + 3];
        }
        if (outF) {
            float4 w = {o0, o1, o2, o3};
            *reinterpret_cast<float4*>(outF + (size_t)bz * cStride
                + (size_t)(m0 + r) * ldC + n0 + c4) = w;
        }
        if (outH) {
            uint2 H, L;
            split2(o0, o1, H.x, L.x);
            split2(o2, o3, H.y, L.y);
            size_t e = (size_t)bz * pStride + (size_t)(m0 + r) * ldP + n0 + c4;
            *reinterpret_cast<uint2*>((char*)outH + e * 2) = H;
            *reinterpret_cast<uint2*>((char*)outL + e * 2) = L;
        }
    }
}

// ---------------------------------------------------------------------------
extern "C" void kernel_launch(void* const* d_in, const int* in_sizes, int n_in,
                              void* d_out, int out_size)
{
    const float* query = (const float*)d_in[0];
    const float* key   = (const float*)d_in[1];
    const float* value = (const float*)d_in[2];
    const float* Wq    = (const float*)d_in[3];
    const float* bq    = (const float*)d_in[4];
    const float* Wk    = (const float*)d_in[5];
    const float* bk    = (const float*)d_in[6];
    const float* Wv    = (const float*)d_in[7];
    const float* bv    = (const float*)d_in[8];
    float* out = (float*)d_out;

    cudaFuncSetAttribute(tc_gemm, cudaFuncAttributeMaxDynamicSharedMemorySize,
                         GEMM_SMEM);

    __nv_bfloat16 *xqh, *xql, *xkh, *xkl, *xvh, *xvl;
    __nv_bfloat16 *wqh, *wql, *wkh, *wkl, *wvh, *wvl;
    __nv_bfloat16 *Qh, *Ql, *Kh, *Kl, *Vth, *Vtl, *Sh, *Sl;
    float *Vf, *Sf;
    cudaGetSymbolAddress((void**)&xqh, g_xqh); cudaGetSymbolAddress((void**)&xql, g_xql);
    cudaGetSymbolAddress((void**)&xkh, g_xkh); cudaGetSymbolAddress((void**)&xkl, g_xkl);
    cudaGetSymbolAddress((void**)&xvh, g_xvh); cudaGetSymbolAddress((void**)&xvl, g_xvl);
    cudaGetSymbolAddress((void**)&wqh, g_wqh); cudaGetSymbolAddress((void**)&wql, g_wql);
    cudaGetSymbolAddress((void**)&wkh, g_wkh); cudaGetSymbolAddress((void**)&wkl, g_wkl);
    cudaGetSymbolAddress((void**)&wvh, g_wvh); cudaGetSymbolAddress((void**)&wvl, g_wvl);
    cudaGetSymbolAddress((void**)&Qh, g_Qh);   cudaGetSymbolAddress((void**)&Ql, g_Ql);
    cudaGetSymbolAddress((void**)&Kh, g_Kh);   cudaGetSymbolAddress((void**)&Kl, g_Kl);
    cudaGetSymbolAddress((void**)&Vf, g_Vf);
    cudaGetSymbolAddress((void**)&Vth, g_Vth); cudaGetSymbolAddress((void**)&Vtl, g_Vtl);
    cudaGetSymbolAddress((void**)&Sf, g_Sf);
    cudaGetSymbolAddress((void**)&Sh, g_Sh);   cudaGetSymbolAddress((void**)&Sl, g_Sl);

    // launch #1: fused packing of all inputs + weights
    PackJob jq = {query, xqh, xql, Wq, wqh, wql};
    PackJob jk = {key,   xkh, xkl, Wk, wkh, wkl};
    PackJob jv = {value, xvh, xvl, Wv, wvh, wvl};
    pack_all<<<dim3(4608, 3), 256>>>(jq, jk, jv);

    // launches #2-4: projections [8192,1024] x W^T + b  (m tiles 64)
    dim3 gp(8, 128, 1);
    tc_gemm<<<gp, NTH, GEMM_SMEM>>>(xqh, xql, wqh, wql, CH, 0, 0, bq, 1.0f,
                                    nullptr, 0, 0, Qh, Ql, CH, 0);
    tc_gemm<<<gp, NTH, GEMM_SMEM>>>(xkh, xkl, wkh, wkl, CH, 0, 0, bk, 1.0f,
                                    nullptr, 0, 0, Kh, Kl, CH, 0);
    tc_gemm<<<gp, NTH, GEMM_SMEM>>>(xvh, xvl, wvh, wvl, CH, 0, 0, bv, 1.0f,
                                    Vf, CH, 0, nullptr, nullptr, 0, 0);

    // launch #5: V -> V^T hi/lo
    transpose_pack<<<dim3(32, 8, 4), 256>>>(Vf, Vth, Vtl);

    // launch #6 (ncu capture target): scores = Q K^T / 32, per batch
    dim3 gs(16, 32, 4);
    tc_gemm<<<gs, NTH, GEMM_SMEM>>>(Qh, Ql, Kh, Kl, CH,
                                    (size_t)SEQ * CH, (size_t)SEQ * CH,
                                    nullptr, 1.0f / 32.0f,
                                    Sf, SEQ, (size_t)SEQ * SEQ,
                                    nullptr, nullptr, 0, 0);

    // launch #7: softmax + repack attn
    softmax_pack<<<BATCH * SEQ, 256>>>(Sf, Sh, Sl);

    // launch #8: out = attn @ V, per batch
    dim3 go(8, 32, 4);
    tc_gemm<<<go, NTH, GEMM_SMEM>>>(Sh, Sl, Vth, Vtl, SEQ,
                                    (size_t)SEQ * SEQ, (size_t)CH * SEQ,
                                    nullptr, 1.0f,
                                    out, CH, (size_t)SEQ * CH,
                                    nullptr, nullptr, 0, 0);
}

// round 11
// speedup vs baseline: 3.0162x; 1.7081x over previous
#include <cuda_runtime.h>
#include <cuda_fp16.h>
#include <mma.h>
#include <cstdint>
#include <cstddef>

using namespace nvcuda;

#define BATCH 4
#define SEQ   2048
#define CH    1024

// GEMM tiling (R10-proven): CTA 64x128, 8 warps (2m x 4n), warp 32x32,
// 256 threads, 2 CTAs/SM. fp16 2-term split: A = Ah+Al (split), B = Bh only.
#define NTH 256
#define BKC 32                        // k per stage
#define BKP 40                        // padded smem ld (elems) -> 80B rows
#define A_BYTES (64 * BKP * 2)        // 5120 B per A array
#define B_BYTES (128 * BKP * 2)       // 10240 B for Bh
#define STAGE_BYTES (2 * A_BYTES + B_BYTES)   // 20480 B
#define NSTAGE 3
#define GEMM_SMEM (NSTAGE * STAGE_BYTES)      // 61440 B (x2 CTAs = 122880)

// ---------------------------------------------------------------------------
// helpers
// ---------------------------------------------------------------------------
__device__ __forceinline__ uint32_t smem_u32(const void* p) {
    uint32_t a;
    asm("{ .reg .u64 t; cvta.to.shared.u64 t, %1; cvt.u32.u64 %0, t; }"
        : "=r"(a) : "l"(p));
    return a;
}

__device__ __forceinline__ void cp_async16(void* dst, const void* src) {
    uint32_t d = smem_u32(dst);
    asm volatile("cp.async.cg.shared.global [%0], [%1], 16;"
                 :: "r"(d), "l"(src) : "memory");
}
__device__ __forceinline__ void cp_commit() {
    asm volatile("cp.async.commit_group;" ::: "memory");
}
template <int N>
__device__ __forceinline__ void cp_wait_group() {
    asm volatile("cp.async.wait_group %0;" :: "n"(N) : "memory");
}

// fp32 pair -> single fp16x2 word
__device__ __forceinline__ uint32_t pack_h2(float a, float b) {
    __half2 h = __floats2half2_rn(a, b);
    return *reinterpret_cast<uint32_t*>(&h);
}
// fp32 pair -> hi/lo fp16x2 words (A-operand split)
__device__ __forceinline__ void split2h(float a, float b, uint32_t& hi, uint32_t& lo) {
    __half ha = __float2half_rn(a);
    __half hb = __float2half_rn(b);
    float ra = a - __half2float(ha);
    float rb = b - __half2float(hb);
    __half2 h = __halves2half2(ha, hb);
    __half2 l = __floats2half2_rn(ra, rb);
    hi = *reinterpret_cast<uint32_t*>(&h);
    lo = *reinterpret_cast<uint32_t*>(&l);
}

// ---------------------------------------------------------------------------
// scratch (row-major everywhere)
// ---------------------------------------------------------------------------
#define NXE ((size_t)BATCH * SEQ * CH)
#define NWE ((size_t)CH * CH)
#define NSE ((size_t)BATCH * SEQ * SEQ)

__device__ __align__(1024) __half g_xqh[NXE], g_xql[NXE];
__device__ __align__(1024) __half g_xkh[NXE], g_xkl[NXE];
__device__ __align__(1024) __half g_xvh[NXE], g_xvl[NXE];
__device__ __align__(1024) __half g_wqh[NWE];            // weights: single fp16
__device__ __align__(1024) __half g_wkh[NWE];
__device__ __align__(1024) __half g_wvh[NWE];
__device__ __align__(1024) __half g_Qh[NXE],  g_Ql[NXE]; // Q: split (A operand)
__device__ __align__(1024) __half g_Kh[NXE];             // K: single (B operand)
__device__ __align__(1024) float  g_Vf[NXE];
__device__ __align__(1024) __half g_Vth[NXE];            // V^T: single (B operand)
__device__ __align__(1024) float  g_Sf[NSE];
__device__ __align__(1024) __half g_Sh[NSE],  g_Sl[NSE]; // attn: split (A operand)

// ---------------------------------------------------------------------------
// fused packing: inputs split (4096 blocks each), weights single (512 each)
// ---------------------------------------------------------------------------
struct PackJob {
    const float* srcX;  __half *xh, *xl;
    const float* srcW;  __half *wh;
};

__global__ void __launch_bounds__(256)
pack_all(PackJob j0, PackJob j1, PackJob j2)
{
    const PackJob& j = (blockIdx.y == 0) ? j0 : (blockIdx.y == 1) ? j1 : j2;
    if (blockIdx.x < 4096) {
        size_t base = ((size_t)blockIdx.x * 256 + threadIdx.x) * 8;
        float4 f0 = *reinterpret_cast<const float4*>(j.srcX + base);
        float4 f1 = *reinterpret_cast<const float4*>(j.srcX + base + 4);
        uint4 H, L;
        split2h(f0.x, f0.y, H.x, L.x);
        split2h(f0.z, f0.w, H.y, L.y);
        split2h(f1.x, f1.y, H.z, L.z);
        split2h(f1.z, f1.w, H.w, L.w);
        *reinterpret_cast<uint4*>((char*)j.xh + base * 2) = H;
        *reinterpret_cast<uint4*>((char*)j.xl + base * 2) = L;
    } else {
        size_t base = ((size_t)(blockIdx.x - 4096) * 256 + threadIdx.x) * 8;
        float4 f0 = *reinterpret_cast<const float4*>(j.srcW + base);
        float4 f1 = *reinterpret_cast<const float4*>(j.srcW + base + 4);
        uint4 H;
        H.x = pack_h2(f0.x, f0.y);
        H.y = pack_h2(f0.z, f0.w);
        H.z = pack_h2(f1.x, f1.y);
        H.w = pack_h2(f1.z, f1.w);
        *reinterpret_cast<uint4*>((char*)j.wh + base * 2) = H;
    }
}

// ---------------------------------------------------------------------------
// V fp32 [B][S][C] -> V^T single fp16 [B][C][S]
// ---------------------------------------------------------------------------
__global__ void __launch_bounds__(256)
transpose_pack(const float* __restrict__ V, __half* __restrict__ Dh)
{
    __shared__ float sb[64 * 129];
    int kc = blockIdx.x, dBlk = blockIdx.y, b = blockIdx.z;
    int seq0 = kc * 64, d0 = dBlk * 128;
    int t = threadIdx.x;
#pragma unroll
    for (int i = 0; i < 8; i++) {
        int idx = t + i * 256;
        int s = idx >> 5, d4 = (idx & 31) * 4;
        float4 v = *reinterpret_cast<const float4*>(
            V + ((size_t)b * SEQ + seq0 + s) * CH + d0 + d4);
        sb[s * 129 + d4 + 0] = v.x;
        sb[s * 129 + d4 + 1] = v.y;
        sb[s * 129 + d4 + 2] = v.z;
        sb[s * 129 + d4 + 3] = v.w;
    }
    __syncthreads();
#pragma unroll
    for (int i = 0; i < 4; i++) {
        int idx = t + i * 256;
        int d = idx >> 3, s8 = (idx & 7) * 8;
        uint4 H;
        H.x = pack_h2(sb[(s8 + 0) * 129 + d], sb[(s8 + 1) * 129 + d]);
        H.y = pack_h2(sb[(s8 + 2) * 129 + d], sb[(s8 + 3) * 129 + d]);
        H.z = pack_h2(sb[(s8 + 4) * 129 + d], sb[(s8 + 5) * 129 + d]);
        H.w = pack_h2(sb[(s8 + 6) * 129 + d], sb[(s8 + 7) * 129 + d]);
        size_t e = ((size_t)b * CH + d0 + d) * SEQ + seq0 + s8;
        *reinterpret_cast<uint4*>((char*)Dh + e * 2) = H;
    }
}

// ---------------------------------------------------------------------------
// softmax over rows of S fp32 [B*S][2048] -> split fp16 hi/lo row-major
// ---------------------------------------------------------------------------
__global__ void __launch_bounds__(256)
softmax_pack(const float* __restrict__ S,
             __half* __restrict__ Dh, __half* __restrict__ Dl)
{
    __shared__ float red[32];
    int rowG = blockIdx.x, t = threadIdx.x;
    const float* row = S + (size_t)rowG * SEQ;
    float4 a = *reinterpret_cast<const float4*>(row + t * 8);
    float4 b2 = *reinterpret_cast<const float4*>(row + t * 8 + 4);
    float v[8] = {a.x, a.y, a.z, a.w, b2.x, b2.y, b2.z, b2.w};

    float m = v[0];
#pragma unroll
    for (int i = 1; i < 8; i++) m = fmaxf(m, v[i]);
#pragma unroll
    for (int o = 16; o > 0; o >>= 1)
        m = fmaxf(m, __shfl_xor_sync(0xffffffffu, m, o));
    if ((t & 31) == 0) red[t >> 5] = m;
    __syncthreads();
    if (t < 32) {
        float x = (t < 8) ? red[t] : -3.4e38f;
#pragma unroll
        for (int o = 4; o > 0; o >>= 1) x = fmaxf(x, __shfl_xor_sync(0xffffffffu, x, o));
        if (t == 0) red[0] = x;
    }
    __syncthreads();
    m = red[0];
    __syncthreads();

    float sum = 0.0f;
#pragma unroll
    for (int i = 0; i < 8; i++) { v[i] = __expf(v[i] - m); sum += v[i]; }
#pragma unroll
    for (int o = 16; o > 0; o >>= 1) sum += __shfl_xor_sync(0xffffffffu, sum, o);
    if ((t & 31) == 0) red[t >> 5] = sum;
    __syncthreads();
    if (t < 32) {
        float x = (t < 8) ? red[t] : 0.0f;
#pragma unroll
        for (int o = 4; o > 0; o >>= 1) x += __shfl_xor_sync(0xffffffffu, x, o);
        if (t == 0) red[0] = x;
    }
    __syncthreads();
    float inv = 1.0f / red[0];

    uint4 H, L;
    split2h(v[0] * inv, v[1] * inv, H.x, L.x);
    split2h(v[2] * inv, v[3] * inv, H.y, L.y);
    split2h(v[4] * inv, v[5] * inv, H.z, L.z);
    split2h(v[6] * inv, v[7] * inv, H.w, L.w);
    size_t e = (size_t)rowG * SEQ + t * 8;
    *reinterpret_cast<uint4*>((char*)Dh + e * 2) = H;
    *reinterpret_cast<uint4*>((char*)Dl + e * 2) = L;
}

// ---------------------------------------------------------------------------
// WMMA fp16 2-term split NT GEMM: C = alpha*(Ah+Al) Bh^T (+bias)
// A split hi/lo fp16, B single fp16. CTA 64x128, 8 warps, 2 CTAs/SM.
// ---------------------------------------------------------------------------
__global__ void __launch_bounds__(NTH, 2)
tc_gemm(const __half* __restrict__ Ah, const __half* __restrict__ Al,
        const __half* __restrict__ Bh,
        int K, size_t aStride, size_t bStride,
        const float* __restrict__ bias, float alpha,
        float* __restrict__ outF, int ldC, size_t cStride,
        __half* __restrict__ outH, __half* __restrict__ outL,
        int ldP, size_t pStride)
{
    extern __shared__ char smem[];
    const int tid = threadIdx.x;
    const int wid = tid >> 5;
    const int bx = blockIdx.x, by = blockIdx.y, bz = blockIdx.z;
    const int m0 = by * 64, n0 = bx * 128;

    const __half* Ahb = Ah + (size_t)bz * aStride + (size_t)m0 * K;
    const __half* Alb = Al + (size_t)bz * aStride + (size_t)m0 * K;
    const __half* Bhb = Bh + (size_t)bz * bStride + (size_t)n0 * K;

    const int nK = K / BKC;

    // stage layout: [Ah 64xBKP][Al 64xBKP][Bh 128xBKP] fp16
    auto load_stage = [&](int s, int c) {
        char* st = smem + s * STAGE_BYTES;
        const int k0 = c * BKC;
        {   // A: 256 jobs (64 rows x 4 segs), 2 cp each (hi, lo)
            int r = tid >> 2, seg = tid & 3;
            size_t goff = (size_t)r * K + k0 + seg * 8;
            uint32_t soff = (uint32_t)r * (BKP * 2) + seg * 16;
            cp_async16(st + soff,           Ahb + goff);
            cp_async16(st + A_BYTES + soff, Alb + goff);
        }
#pragma unroll
        for (int i = 0; i < 2; i++) {   // B: 512 jobs (128 rows x 4 segs)
            int job = tid + i * NTH;
            int r = job >> 2, seg = job & 3;
            size_t goff = (size_t)r * K + k0 + seg * 8;
            uint32_t soff = (uint32_t)r * (BKP * 2) + seg * 16;
            cp_async16(st + 2 * A_BYTES + soff, Bhb + goff);
        }
    };

    wmma::fragment<wmma::accumulator, 16, 16, 16, float> acc[2][2];
#pragma unroll
    for (int i = 0; i < 2; i++)
#pragma unroll
        for (int j = 0; j < 2; j++) wmma::fill_fragment(acc[i][j], 0.0f);

#pragma unroll
    for (int s = 0; s < NSTAGE; s++) { load_stage(s, s); cp_commit(); }

    const int wm = (wid & 1) * 32;            // 2 m-warps
    const int wn = (wid >> 1) * 32;           // 4 n-warps

    for (int c = 0; c < nK; c++) {
        cp_wait_group<NSTAGE - 1>();
        __syncthreads();

        const char* st = smem + (c % NSTAGE) * STAGE_BYTES;
        const __half* As_h = (const __half*)st;
        const __half* As_l = (const __half*)(st + A_BYTES);
        const __half* Bs_h = (const __half*)(st + 2 * A_BYTES);

#pragma unroll
        for (int ks = 0; ks < 2; ks++) {
            wmma::fragment<wmma::matrix_a, 16, 16, 16, __half, wmma::row_major> fah[2], fal[2];
            wmma::fragment<wmma::matrix_b, 16, 16, 16, __half, wmma::col_major> fbh[2];
#pragma unroll
            for (int i = 0; i < 2; i++) {
                wmma::load_matrix_sync(fah[i], As_h + (wm + i * 16) * BKP + ks * 16, BKP);
                wmma::load_matrix_sync(fal[i], As_l + (wm + i * 16) * BKP + ks * 16, BKP);
            }
#pragma unroll
            for (int j = 0; j < 2; j++)
                wmma::load_matrix_sync(fbh[j], Bs_h + (wn + j * 16) * BKP + ks * 16, BKP);
#pragma unroll
            for (int i = 0; i < 2; i++)
#pragma unroll
                for (int j = 0; j < 2; j++) {
                    wmma::mma_sync(acc[i][j], fah[i], fbh[j], acc[i][j]);
                    wmma::mma_sync(acc[i][j], fal[i], fbh[j], acc[i][j]);
                }
        }
        __syncthreads();
        if (c + NSTAGE < nK) load_stage(c % NSTAGE, c + NSTAGE);
        cp_commit();
    }
    cp_wait_group<0>();
    __syncthreads();

    // epilogue via smem staging (64x128 fp32 = 32KB)
    float* Cs = (float*)smem;
#pragma unroll
    for (int i = 0; i < 2; i++)
#pragma unroll
        for (int j = 0; j < 2; j++)
            wmma::store_matrix_sync(Cs + (wm + i * 16) * 128 + wn + j * 16,
                                    acc[i][j], 128, wmma::mem_row_major);
    __syncthreads();

#pragma unroll
    for (int it = 0; it < 8; it++) {
        int g = tid + it * NTH;               // 2048 float4 groups
        int r = g >> 5, c4 = (g & 31) * 4;
        float4 v = *reinterpret_cast<const float4*>(Cs + r * 128 + c4);
        float o0 = v.x * alpha, o1 = v.y * alpha;
        float o2 = v.z * alpha, o3 = v.w * alpha;
        if (bias) {
            o0 += bias[n0 + c4 + 0];
            o1 += bias[n0 + c4 + 1];
            o2 += bias[n0 + c4 + 2];
            o3 += bias[n0 + c4 + 3];
        }
        if (outF) {
            float4 w = {o0, o1, o2, o3};
            *reinterpret_cast<float4*>(outF + (size_t)bz * cStride
                + (size_t)(m0 + r) * ldC + n0 + c4) = w;
        }
        if (outH) {
            size_t e = (size_t)bz * pStride + (size_t)(m0 + r) * ldP + n0 + c4;
            if (outL) {                      // split hi/lo (A operand)
                uint2 H, L;
                split2h(o0, o1, H.x, L.x);
                split2h(o2, o3, H.y, L.y);
                *reinterpret_cast<uint2*>((char*)outH + e * 2) = H;
                *reinterpret_cast<uint2*>((char*)outL + e * 2) = L;
            } else {                         // single fp16 (B operand)
                uint2 H;
                H.x = pack_h2(o0, o1);
                H.y = pack_h2(o2, o3);
                *reinterpret_cast<uint2*>((char*)outH + e * 2) = H;
            }
        }
    }
}

// ---------------------------------------------------------------------------
extern "C" void kernel_launch(void* const* d_in, const int* in_sizes, int n_in,
                              void* d_out, int out_size)
{
    const float* query = (const float*)d_in[0];
    const float* key   = (const float*)d_in[1];
    const float* value = (const float*)d_in[2];
    const float* Wq    = (const float*)d_in[3];
    const float* bq    = (const float*)d_in[4];
    const float* Wk    = (const float*)d_in[5];
    const float* bk    = (const float*)d_in[6];
    const float* Wv    = (const float*)d_in[7];
    const float* bv    = (const float*)d_in[8];
    float* out = (float*)d_out;

    cudaFuncSetAttribute(tc_gemm, cudaFuncAttributeMaxDynamicSharedMemorySize,
                         GEMM_SMEM);

    __half *xqh, *xql, *xkh, *xkl, *xvh, *xvl;
    __half *wqh, *wkh, *wvh;
    __half *Qh, *Ql, *Kh, *Vth, *Sh, *Sl;
    float *Vf, *Sf;
    cudaGetSymbolAddress((void**)&xqh, g_xqh); cudaGetSymbolAddress((void**)&xql, g_xql);
    cudaGetSymbolAddress((void**)&xkh, g_xkh); cudaGetSymbolAddress((void**)&xkl, g_xkl);
    cudaGetSymbolAddress((void**)&xvh, g_xvh); cudaGetSymbolAddress((void**)&xvl, g_xvl);
    cudaGetSymbolAddress((void**)&wqh, g_wqh);
    cudaGetSymbolAddress((void**)&wkh, g_wkh);
    cudaGetSymbolAddress((void**)&wvh, g_wvh);
    cudaGetSymbolAddress((void**)&Qh, g_Qh);   cudaGetSymbolAddress((void**)&Ql, g_Ql);
    cudaGetSymbolAddress((void**)&Kh, g_Kh);
    cudaGetSymbolAddress((void**)&Vf, g_Vf);
    cudaGetSymbolAddress((void**)&Vth, g_Vth);
    cudaGetSymbolAddress((void**)&Sf, g_Sf);
    cudaGetSymbolAddress((void**)&Sh, g_Sh);   cudaGetSymbolAddress((void**)&Sl, g_Sl);

    // launch #1: fused packing (inputs split, weights single)
    PackJob jq = {query, xqh, xql, Wq, wqh};
    PackJob jk = {key,   xkh, xkl, Wk, wkh};
    PackJob jv = {value, xvh, xvl, Wv, wvh};
    pack_all<<<dim3(4608, 3), 256>>>(jq, jk, jv);

    // launches #2-4: projections [8192,1024] x W^T + b  (m tiles 64)
    dim3 gp(8, 128, 1);
    tc_gemm<<<gp, NTH, GEMM_SMEM>>>(xqh, xql, wqh, CH, 0, 0, bq, 1.0f,
                                    nullptr, 0, 0, Qh, Ql, CH, 0);
    tc_gemm<<<gp, NTH, GEMM_SMEM>>>(xkh, xkl, wkh, CH, 0, 0, bk, 1.0f,
                                    nullptr, 0, 0, Kh, nullptr, CH, 0);
    tc_gemm<<<gp, NTH, GEMM_SMEM>>>(xvh, xvl, wvh, CH, 0, 0, bv, 1.0f,
                                    Vf, CH, 0, nullptr, nullptr, 0, 0);

    // launch #5: V -> V^T single fp16
    transpose_pack<<<dim3(32, 8, 4), 256>>>(Vf, Vth);

    // launch #6 (ncu capture target): scores = Q K^T / 32, per batch
    dim3 gs(16, 32, 4);
    tc_gemm<<<gs, NTH, GEMM_SMEM>>>(Qh, Ql, Kh, CH,
                                    (size_t)SEQ * CH, (size_t)SEQ * CH,
                                    nullptr, 1.0f / 32.0f,
                                    Sf, SEQ, (size_t)SEQ * SEQ,
                                    nullptr, nullptr, 0, 0);

    // launch #7: softmax + split-pack attn
    softmax_pack<<<BATCH * SEQ, 256>>>(Sf, Sh, Sl);

    // launch #8: out = attn @ V, per batch
    dim3 go(8, 32, 4);
    tc_gemm<<<go, NTH, GEMM_SMEM>>>(Sh, Sl, Vth, SEQ,
                                    (size_t)SEQ * SEQ, (size_t)CH * SEQ,
                                    nullptr, 1.0f,
                                    out, CH, (size_t)SEQ * CH,
                                    nullptr, nullptr, 0, 0);
}

// round 12
// speedup vs baseline: 4.2355x; 1.4042x over previous
#include <cuda_runtime.h>
#include <cuda_fp16.h>
#include <mma.h>
#include <cstdint>
#include <cstddef>

using namespace nvcuda;

#define BATCH 4
#define SEQ   2048
#define CH    1024

// GEMM tiling (R10/R11-proven): CTA 64x128, 8 warps (2m x 4n), warp 32x32,
// 256 threads, 2 CTAs/SM. Pure single-fp16 operands (1-term).
#define NTH 256
#define BKC 32                        // k per stage
#define BKP 40                        // padded smem ld (elems) -> 80B rows
#define A_BYTES (64 * BKP * 2)        // 5120 B
#define B_BYTES (128 * BKP * 2)       // 10240 B
#define STAGE_BYTES (A_BYTES + B_BYTES)       // 15360 B
#define NSTAGE 3
#define GEMM_SMEM (NSTAGE * STAGE_BYTES)      // 46080 B (x2 CTAs = 92160)

// ---------------------------------------------------------------------------
// helpers
// ---------------------------------------------------------------------------
__device__ __forceinline__ uint32_t smem_u32(const void* p) {
    uint32_t a;
    asm("{ .reg .u64 t; cvta.to.shared.u64 t, %1; cvt.u32.u64 %0, t; }"
        : "=r"(a) : "l"(p));
    return a;
}

__device__ __forceinline__ void cp_async16(void* dst, const void* src) {
    uint32_t d = smem_u32(dst);
    asm volatile("cp.async.cg.shared.global [%0], [%1], 16;"
                 :: "r"(d), "l"(src) : "memory");
}
__device__ __forceinline__ void cp_commit() {
    asm volatile("cp.async.commit_group;" ::: "memory");
}
template <int N>
__device__ __forceinline__ void cp_wait_group() {
    asm volatile("cp.async.wait_group %0;" :: "n"(N) : "memory");
}

// fp32 pair -> fp16x2 word
__device__ __forceinline__ uint32_t pack_h2(float a, float b) {
    __half2 h = __floats2half2_rn(a, b);
    return *reinterpret_cast<uint32_t*>(&h);
}

// ---------------------------------------------------------------------------
// scratch (row-major everywhere, all single fp16 except fp32 staging)
// ---------------------------------------------------------------------------
#define NXE ((size_t)BATCH * SEQ * CH)
#define NWE ((size_t)CH * CH)
#define NSE ((size_t)BATCH * SEQ * SEQ)

__device__ __align__(1024) __half g_xq[NXE], g_xk[NXE], g_xv[NXE];
__device__ __align__(1024) __half g_wq[NWE], g_wk[NWE], g_wv[NWE];
__device__ __align__(1024) __half g_Q[NXE],  g_K[NXE];
__device__ __align__(1024) float  g_Vf[NXE];
__device__ __align__(1024) __half g_Vt[NXE];
__device__ __align__(1024) float  g_Sf[NSE];
__device__ __align__(1024) __half g_S[NSE];

// ---------------------------------------------------------------------------
// fused packing: 3 inputs (4096 blocks) + 3 weights (512 blocks), single fp16
// ---------------------------------------------------------------------------
struct PackJob {
    const float* srcX;  __half* xh;
    const float* srcW;  __half* wh;
};

__global__ void __launch_bounds__(256)
pack_all(PackJob j0, PackJob j1, PackJob j2)
{
    const PackJob& j = (blockIdx.y == 0) ? j0 : (blockIdx.y == 1) ? j1 : j2;
    const float* src;
    __half* dst;
    size_t base;
    if (blockIdx.x < 4096) {
        src = j.srcX; dst = j.xh;
        base = ((size_t)blockIdx.x * 256 + threadIdx.x) * 8;
    } else {
        src = j.srcW; dst = j.wh;
        base = ((size_t)(blockIdx.x - 4096) * 256 + threadIdx.x) * 8;
    }
    float4 f0 = *reinterpret_cast<const float4*>(src + base);
    float4 f1 = *reinterpret_cast<const float4*>(src + base + 4);
    uint4 H;
    H.x = pack_h2(f0.x, f0.y);
    H.y = pack_h2(f0.z, f0.w);
    H.z = pack_h2(f1.x, f1.y);
    H.w = pack_h2(f1.z, f1.w);
    *reinterpret_cast<uint4*>((char*)dst + base * 2) = H;
}

// ---------------------------------------------------------------------------
// V fp32 [B][S][C] -> V^T fp16 [B][C][S]
// ---------------------------------------------------------------------------
__global__ void __launch_bounds__(256)
transpose_pack(const float* __restrict__ V, __half* __restrict__ Dh)
{
    __shared__ float sb[64 * 129];
    int kc = blockIdx.x, dBlk = blockIdx.y, b = blockIdx.z;
    int seq0 = kc * 64, d0 = dBlk * 128;
    int t = threadIdx.x;
#pragma unroll
    for (int i = 0; i < 8; i++) {
        int idx = t + i * 256;
        int s = idx >> 5, d4 = (idx & 31) * 4;
        float4 v = *reinterpret_cast<const float4*>(
            V + ((size_t)b * SEQ + seq0 + s) * CH + d0 + d4);
        sb[s * 129 + d4 + 0] = v.x;
        sb[s * 129 + d4 + 1] = v.y;
        sb[s * 129 + d4 + 2] = v.z;
        sb[s * 129 + d4 + 3] = v.w;
    }
    __syncthreads();
#pragma unroll
    for (int i = 0; i < 4; i++) {
        int idx = t + i * 256;
        int d = idx >> 3, s8 = (idx & 7) * 8;
        uint4 H;
        H.x = pack_h2(sb[(s8 + 0) * 129 + d], sb[(s8 + 1) * 129 + d]);
        H.y = pack_h2(sb[(s8 + 2) * 129 + d], sb[(s8 + 3) * 129 + d]);
        H.z = pack_h2(sb[(s8 + 4) * 129 + d], sb[(s8 + 5) * 129 + d]);
        H.w = pack_h2(sb[(s8 + 6) * 129 + d], sb[(s8 + 7) * 129 + d]);
        size_t e = ((size_t)b * CH + d0 + d) * SEQ + seq0 + s8;
        *reinterpret_cast<uint4*>((char*)Dh + e * 2) = H;
    }
}

// ---------------------------------------------------------------------------
// softmax over rows of S fp32 [B*S][2048] -> single fp16 row-major
// ---------------------------------------------------------------------------
__global__ void __launch_bounds__(256)
softmax_pack(const float* __restrict__ S, __half* __restrict__ Dh)
{
    __shared__ float red[32];
    int rowG = blockIdx.x, t = threadIdx.x;
    const float* row = S + (size_t)rowG * SEQ;
    float4 a = *reinterpret_cast<const float4*>(row + t * 8);
    float4 b2 = *reinterpret_cast<const float4*>(row + t * 8 + 4);
    float v[8] = {a.x, a.y, a.z, a.w, b2.x, b2.y, b2.z, b2.w};

    float m = v[0];
#pragma unroll
    for (int i = 1; i < 8; i++) m = fmaxf(m, v[i]);
#pragma unroll
    for (int o = 16; o > 0; o >>= 1)
        m = fmaxf(m, __shfl_xor_sync(0xffffffffu, m, o));
    if ((t & 31) == 0) red[t >> 5] = m;
    __syncthreads();
    if (t < 32) {
        float x = (t < 8) ? red[t] : -3.4e38f;
#pragma unroll
        for (int o = 4; o > 0; o >>= 1) x = fmaxf(x, __shfl_xor_sync(0xffffffffu, x, o));
        if (t == 0) red[0] = x;
    }
    __syncthreads();
    m = red[0];
    __syncthreads();

    float sum = 0.0f;
#pragma unroll
    for (int i = 0; i < 8; i++) { v[i] = __expf(v[i] - m); sum += v[i]; }
#pragma unroll
    for (int o = 16; o > 0; o >>= 1) sum += __shfl_xor_sync(0xffffffffu, sum, o);
    if ((t & 31) == 0) red[t >> 5] = sum;
    __syncthreads();
    if (t < 32) {
        float x = (t < 8) ? red[t] : 0.0f;
#pragma unroll
        for (int o = 4; o > 0; o >>= 1) x += __shfl_xor_sync(0xffffffffu, x, o);
        if (t == 0) red[0] = x;
    }
    __syncthreads();
    float inv = 1.0f / red[0];

    uint4 H;
    H.x = pack_h2(v[0] * inv, v[1] * inv);
    H.y = pack_h2(v[2] * inv, v[3] * inv);
    H.z = pack_h2(v[4] * inv, v[5] * inv);
    H.w = pack_h2(v[6] * inv, v[7] * inv);
    size_t e = (size_t)rowG * SEQ + t * 8;
    *reinterpret_cast<uint4*>((char*)Dh + e * 2) = H;
}

// ---------------------------------------------------------------------------
// WMMA fp16 NT GEMM (single-term): C = alpha * A B^T (+bias)
// CTA 64x128, 8 warps (2m x 4n), warp 32x32, 2 CTAs/SM, NSTAGE=3.
// ---------------------------------------------------------------------------
__global__ void __launch_bounds__(NTH, 2)
tc_gemm(const __half* __restrict__ Ah, const __half* __restrict__ Bh,
        int K, size_t aStride, size_t bStride,
        const float* __restrict__ bias, float alpha,
        float* __restrict__ outF, int ldC, size_t cStride,
        __half* __restrict__ outH, int ldP, size_t pStride)
{
    extern __shared__ char smem[];
    const int tid = threadIdx.x;
    const int wid = tid >> 5;
    const int bx = blockIdx.x, by = blockIdx.y, bz = blockIdx.z;
    const int m0 = by * 64, n0 = bx * 128;

    const __half* Ahb = Ah + (size_t)bz * aStride + (size_t)m0 * K;
    const __half* Bhb = Bh + (size_t)bz * bStride + (size_t)n0 * K;

    const int nK = K / BKC;

    // stage layout: [A 64xBKP][B 128xBKP] fp16
    auto load_stage = [&](int s, int c) {
        char* st = smem + s * STAGE_BYTES;
        const int k0 = c * BKC;
        {   // A: 256 jobs (64 rows x 4 segs)
            int r = tid >> 2, seg = tid & 3;
            size_t goff = (size_t)r * K + k0 + seg * 8;
            uint32_t soff = (uint32_t)r * (BKP * 2) + seg * 16;
            cp_async16(st + soff, Ahb + goff);
        }
#pragma unroll
        for (int i = 0; i < 2; i++) {   // B: 512 jobs (128 rows x 4 segs)
            int job = tid + i * NTH;
            int r = job >> 2, seg = job & 3;
            size_t goff = (size_t)r * K + k0 + seg * 8;
            uint32_t soff = (uint32_t)r * (BKP * 2) + seg * 16;
            cp_async16(st + A_BYTES + soff, Bhb + goff);
        }
    };

    wmma::fragment<wmma::accumulator, 16, 16, 16, float> acc[2][2];
#pragma unroll
    for (int i = 0; i < 2; i++)
#pragma unroll
        for (int j = 0; j < 2; j++) wmma::fill_fragment(acc[i][j], 0.0f);

#pragma unroll
    for (int s = 0; s < NSTAGE; s++) { load_stage(s, s); cp_commit(); }

    const int wm = (wid & 1) * 32;            // 2 m-warps
    const int wn = (wid >> 1) * 32;           // 4 n-warps

    for (int c = 0; c < nK; c++) {
        cp_wait_group<NSTAGE - 1>();
        __syncthreads();

        const char* st = smem + (c % NSTAGE) * STAGE_BYTES;
        const __half* As = (const __half*)st;
        const __half* Bs = (const __half*)(st + A_BYTES);

#pragma unroll
        for (int ks = 0; ks < 2; ks++) {
            wmma::fragment<wmma::matrix_a, 16, 16, 16, __half, wmma::row_major> fa[2];
            wmma::fragment<wmma::matrix_b, 16, 16, 16, __half, wmma::col_major> fb[2];
#pragma unroll
            for (int i = 0; i < 2; i++)
                wmma::load_matrix_sync(fa[i], As + (wm + i * 16) * BKP + ks * 16, BKP);
#pragma unroll
            for (int j = 0; j < 2; j++)
                wmma::load_matrix_sync(fb[j], Bs + (wn + j * 16) * BKP + ks * 16, BKP);
#pragma unroll
            for (int i = 0; i < 2; i++)
#pragma unroll
                for (int j = 0; j < 2; j++)
                    wmma::mma_sync(acc[i][j], fa[i], fb[j], acc[i][j]);
        }
        __syncthreads();
        if (c + NSTAGE < nK) load_stage(c % NSTAGE, c + NSTAGE);
        cp_commit();
    }
    cp_wait_group<0>();
    __syncthreads();

    // epilogue via smem staging (64x128 fp32 = 32KB <= 45KB)
    float* Cs = (float*)smem;
#pragma unroll
    for (int i = 0; i < 2; i++)
#pragma unroll
        for (int j = 0; j < 2; j++)
            wmma::store_matrix_sync(Cs + (wm + i * 16) * 128 + wn + j * 16,
                                    acc[i][j], 128, wmma::mem_row_major);
    __syncthreads();

#pragma unroll
    for (int it = 0; it < 8; it++) {
        int g = tid + it * NTH;               // 2048 float4 groups
        int r = g >> 5, c4 = (g & 31) * 4;
        float4 v = *reinterpret_cast<const float4*>(Cs + r * 128 + c4);
        float o0 = v.x * alpha, o1 = v.y * alpha;
        float o2 = v.z * alpha, o3 = v.w * alpha;
        if (bias) {
            o0 += bias[n0 + c4 + 0];
            o1 += bias[n0 + c4 + 1];
            o2 += bias[n0 + c4 + 2];
            o3 += bias[n0 + c4 + 3];
        }
        if (outF) {
            float4 w = {o0, o1, o2, o3};
            *reinterpret_cast<float4*>(outF + (size_t)bz * cStride
                + (size_t)(m0 + r) * ldC + n0 + c4) = w;
        }
        if (outH) {
            uint2 H;
            H.x = pack_h2(o0, o1);
            H.y = pack_h2(o2, o3);
            size_t e = (size_t)bz * pStride + (size_t)(m0 + r) * ldP + n0 + c4;
            *reinterpret_cast<uint2*>((char*)outH + e * 2) = H;
        }
    }
}

// ---------------------------------------------------------------------------
extern "C" void kernel_launch(void* const* d_in, const int* in_sizes, int n_in,
                              void* d_out, int out_size)
{
    const float* query = (const float*)d_in[0];
    const float* key   = (const float*)d_in[1];
    const float* value = (const float*)d_in[2];
    const float* Wq    = (const float*)d_in[3];
    const float* bq    = (const float*)d_in[4];
    const float* Wk    = (const float*)d_in[5];
    const float* bk    = (const float*)d_in[6];
    const float* Wv    = (const float*)d_in[7];
    const float* bv    = (const float*)d_in[8];
    float* out = (float*)d_out;

    cudaFuncSetAttribute(tc_gemm, cudaFuncAttributeMaxDynamicSharedMemorySize,
                         GEMM_SMEM);

    __half *xq, *xk, *xv, *wq, *wk, *wv, *Q, *K, *Vt, *S;
    float *Vf, *Sf;
    cudaGetSymbolAddress((void**)&xq, g_xq);
    cudaGetSymbolAddress((void**)&xk, g_xk);
    cudaGetSymbolAddress((void**)&xv, g_xv);
    cudaGetSymbolAddress((void**)&wq, g_wq);
    cudaGetSymbolAddress((void**)&wk, g_wk);
    cudaGetSymbolAddress((void**)&wv, g_wv);
    cudaGetSymbolAddress((void**)&Q, g_Q);
    cudaGetSymbolAddress((void**)&K, g_K);
    cudaGetSymbolAddress((void**)&Vf, g_Vf);
    cudaGetSymbolAddress((void**)&Vt, g_Vt);
    cudaGetSymbolAddress((void**)&Sf, g_Sf);
    cudaGetSymbolAddress((void**)&S, g_S);

    // launch #1: fused packing (all single fp16)
    PackJob jq = {query, xq, Wq, wq};
    PackJob jk = {key,   xk, Wk, wk};
    PackJob jv = {value, xv, Wv, wv};
    pack_all<<<dim3(4608, 3), 256>>>(jq, jk, jv);

    // launches #2-4: projections [8192,1024] x W^T + b  (m tiles 64)
    dim3 gp(8, 128, 1);
    tc_gemm<<<gp, NTH, GEMM_SMEM>>>(xq, wq, CH, 0, 0, bq, 1.0f,
                                    nullptr, 0, 0, Q, CH, 0);
    tc_gemm<<<gp, NTH, GEMM_SMEM>>>(xk, wk, CH, 0, 0, bk, 1.0f,
                                    nullptr, 0, 0, K, CH, 0);
    tc_gemm<<<gp, NTH, GEMM_SMEM>>>(xv, wv, CH, 0, 0, bv, 1.0f,
                                    Vf, CH, 0, nullptr, 0, 0);

    // launch #5: V -> V^T fp16
    transpose_pack<<<dim3(32, 8, 4), 256>>>(Vf, Vt);

    // launch #6 (ncu capture target): scores = Q K^T / 32, per batch
    dim3 gs(16, 32, 4);
    tc_gemm<<<gs, NTH, GEMM_SMEM>>>(Q, K, CH,
                                    (size_t)SEQ * CH, (size_t)SEQ * CH,
                                    nullptr, 1.0f / 32.0f,
                                    Sf, SEQ, (size_t)SEQ * SEQ,
                                    nullptr, 0, 0);

    // launch #7: softmax + fp16 pack
    softmax_pack<<<BATCH * SEQ, 256>>>(Sf, S);

    // launch #8: out = attn @ V, per batch
    dim3 go(8, 32, 4);
    tc_gemm<<<go, NTH, GEMM_SMEM>>>(S, Vt, SEQ,
                                    (size_t)SEQ * SEQ, (size_t)CH * SEQ,
                                    nullptr, 1.0f,
                                    out, CH, (size_t)SEQ * CH,
                                    nullptr, 0, 0);
}

// round 13
// speedup vs baseline: 4.5450x; 1.0731x over previous
#include <cuda_runtime.h>
#include <cuda_fp16.h>
#include <mma.h>
#include <cstdint>
#include <cstddef>

using namespace nvcuda;

#define BATCH 4
#define SEQ   2048
#define CH    1024

// GEMM tiling: CTA 128x128, 8 warps (4m x 2n), warp 32x64, 256 threads,
// 2 CTAs/SM. Single-fp16 operands.
#define NTH 256
#define BKC 32                        // k per stage
#define BKP 40                        // padded smem ld (elems) -> 80B rows
#define A_BYTES (128 * BKP * 2)       // 10240 B
#define B_BYTES (128 * BKP * 2)       // 10240 B
#define STAGE_BYTES (A_BYTES + B_BYTES)       // 20480 B
#define NSTAGE 3
#define GEMM_SMEM (NSTAGE * STAGE_BYTES)      // 61440 B (x2 CTAs = 122880)

// ---------------------------------------------------------------------------
// helpers
// ---------------------------------------------------------------------------
__device__ __forceinline__ uint32_t smem_u32(const void* p) {
    uint32_t a;
    asm("{ .reg .u64 t; cvta.to.shared.u64 t, %1; cvt.u32.u64 %0, t; }"
        : "=r"(a) : "l"(p));
    return a;
}

__device__ __forceinline__ void cp_async16(void* dst, const void* src) {
    uint32_t d = smem_u32(dst);
    asm volatile("cp.async.cg.shared.global [%0], [%1], 16;"
                 :: "r"(d), "l"(src) : "memory");
}
__device__ __forceinline__ void cp_commit() {
    asm volatile("cp.async.commit_group;" ::: "memory");
}
template <int N>
__device__ __forceinline__ void cp_wait_group() {
    asm volatile("cp.async.wait_group %0;" :: "n"(N) : "memory");
}

// fp32 pair -> fp16x2 word
__device__ __forceinline__ uint32_t pack_h2(float a, float b) {
    __half2 h = __floats2half2_rn(a, b);
    return *reinterpret_cast<uint32_t*>(&h);
}

// ---------------------------------------------------------------------------
// scratch
// ---------------------------------------------------------------------------
#define NXE ((size_t)BATCH * SEQ * CH)
#define NWE ((size_t)CH * CH)
#define NSE ((size_t)BATCH * SEQ * SEQ)

__device__ __align__(1024) __half g_xq[NXE], g_xk[NXE], g_xv[NXE];
__device__ __align__(1024) __half g_wq[NWE], g_wk[NWE], g_wv[NWE];
__device__ __align__(1024) __half g_Q[NXE],  g_K[NXE];
__device__ __align__(1024) float  g_Vf[NXE];
__device__ __align__(1024) __half g_Vt[NXE];
__device__ __align__(1024) float  g_Sf[NSE];
__device__ __align__(1024) __half g_S[NSE];

// ---------------------------------------------------------------------------
// fused packing: 3 inputs (4096 blocks) + 3 weights (512 blocks), single fp16
// ---------------------------------------------------------------------------
struct PackJob {
    const float* srcX;  __half* xh;
    const float* srcW;  __half* wh;
};

__global__ void __launch_bounds__(256)
pack_all(PackJob j0, PackJob j1, PackJob j2)
{
    const PackJob& j = (blockIdx.y == 0) ? j0 : (blockIdx.y == 1) ? j1 : j2;
    const float* src;
    __half* dst;
    size_t base;
    if (blockIdx.x < 4096) {
        src = j.srcX; dst = j.xh;
        base = ((size_t)blockIdx.x * 256 + threadIdx.x) * 8;
    } else {
        src = j.srcW; dst = j.wh;
        base = ((size_t)(blockIdx.x - 4096) * 256 + threadIdx.x) * 8;
    }
    float4 f0 = *reinterpret_cast<const float4*>(src + base);
    float4 f1 = *reinterpret_cast<const float4*>(src + base + 4);
    uint4 H;
    H.x = pack_h2(f0.x, f0.y);
    H.y = pack_h2(f0.z, f0.w);
    H.z = pack_h2(f1.x, f1.y);
    H.w = pack_h2(f1.z, f1.w);
    *reinterpret_cast<uint4*>((char*)dst + base * 2) = H;
}

// ---------------------------------------------------------------------------
// V fp32 [B][S][C] -> V^T fp16 [B][C][S]
// ---------------------------------------------------------------------------
__global__ void __launch_bounds__(256)
transpose_pack(const float* __restrict__ V, __half* __restrict__ Dh)
{
    __shared__ float sb[64 * 129];
    int kc = blockIdx.x, dBlk = blockIdx.y, b = blockIdx.z;
    int seq0 = kc * 64, d0 = dBlk * 128;
    int t = threadIdx.x;
#pragma unroll
    for (int i = 0; i < 8; i++) {
        int idx = t + i * 256;
        int s = idx >> 5, d4 = (idx & 31) * 4;
        float4 v = *reinterpret_cast<const float4*>(
            V + ((size_t)b * SEQ + seq0 + s) * CH + d0 + d4);
        sb[s * 129 + d4 + 0] = v.x;
        sb[s * 129 + d4 + 1] = v.y;
        sb[s * 129 + d4 + 2] = v.z;
        sb[s * 129 + d4 + 3] = v.w;
    }
    __syncthreads();
#pragma unroll
    for (int i = 0; i < 4; i++) {
        int idx = t + i * 256;
        int d = idx >> 3, s8 = (idx & 7) * 8;
        uint4 H;
        H.x = pack_h2(sb[(s8 + 0) * 129 + d], sb[(s8 + 1) * 129 + d]);
        H.y = pack_h2(sb[(s8 + 2) * 129 + d], sb[(s8 + 3) * 129 + d]);
        H.z = pack_h2(sb[(s8 + 4) * 129 + d], sb[(s8 + 5) * 129 + d]);
        H.w = pack_h2(sb[(s8 + 6) * 129 + d], sb[(s8 + 7) * 129 + d]);
        size_t e = ((size_t)b * CH + d0 + d) * SEQ + seq0 + s8;
        *reinterpret_cast<uint4*>((char*)Dh + e * 2) = H;
    }
}

// ---------------------------------------------------------------------------
// softmax over rows of S fp32 [B*S][2048] -> single fp16 row-major
// ---------------------------------------------------------------------------
__global__ void __launch_bounds__(256)
softmax_pack(const float* __restrict__ S, __half* __restrict__ Dh)
{
    __shared__ float red[32];
    int rowG = blockIdx.x, t = threadIdx.x;
    const float* row = S + (size_t)rowG * SEQ;
    float4 a = *reinterpret_cast<const float4*>(row + t * 8);
    float4 b2 = *reinterpret_cast<const float4*>(row + t * 8 + 4);
    float v[8] = {a.x, a.y, a.z, a.w, b2.x, b2.y, b2.z, b2.w};

    float m = v[0];
#pragma unroll
    for (int i = 1; i < 8; i++) m = fmaxf(m, v[i]);
#pragma unroll
    for (int o = 16; o > 0; o >>= 1)
        m = fmaxf(m, __shfl_xor_sync(0xffffffffu, m, o));
    if ((t & 31) == 0) red[t >> 5] = m;
    __syncthreads();
    if (t < 32) {
        float x = (t < 8) ? red[t] : -3.4e38f;
#pragma unroll
        for (int o = 4; o > 0; o >>= 1) x = fmaxf(x, __shfl_xor_sync(0xffffffffu, x, o));
        if (t == 0) red[0] = x;
    }
    __syncthreads();
    m = red[0];
    __syncthreads();

    float sum = 0.0f;
#pragma unroll
    for (int i = 0; i < 8; i++) { v[i] = __expf(v[i] - m); sum += v[i]; }
#pragma unroll
    for (int o = 16; o > 0; o >>= 1) sum += __shfl_xor_sync(0xffffffffu, sum, o);
    if ((t & 31) == 0) red[t >> 5] = sum;
    __syncthreads();
    if (t < 32) {
        float x = (t < 8) ? red[t] : 0.0f;
#pragma unroll
        for (int o = 4; o > 0; o >>= 1) x += __shfl_xor_sync(0xffffffffu, x, o);
        if (t == 0) red[0] = x;
    }
    __syncthreads();
    float inv = 1.0f / red[0];

    uint4 H;
    H.x = pack_h2(v[0] * inv, v[1] * inv);
    H.y = pack_h2(v[2] * inv, v[3] * inv);
    H.z = pack_h2(v[4] * inv, v[5] * inv);
    H.w = pack_h2(v[6] * inv, v[7] * inv);
    size_t e = (size_t)rowG * SEQ + t * 8;
    *reinterpret_cast<uint4*>((char*)Dh + e * 2) = H;
}

// ---------------------------------------------------------------------------
// WMMA fp16 NT GEMM: C = alpha * A B^T (+bias)
// CTA 128x128, 8 warps (4m x 2n), warp 32x64, 2 CTAs/SM, NSTAGE=3.
// Two-pass epilogue through 32KB smem staging.
// ---------------------------------------------------------------------------
__global__ void __launch_bounds__(NTH, 2)
tc_gemm(const __half* __restrict__ Ah, const __half* __restrict__ Bh,
        int K, size_t aStride, size_t bStride,
        const float* __restrict__ bias, float alpha,
        float* __restrict__ outF, int ldC, size_t cStride,
        __half* __restrict__ outH, int ldP, size_t pStride)
{
    extern __shared__ char smem[];
    const int tid = threadIdx.x;
    const int wid = tid >> 5;
    const int bx = blockIdx.x, by = blockIdx.y, bz = blockIdx.z;
    const int m0 = by * 128, n0 = bx * 128;

    const __half* Ahb = Ah + (size_t)bz * aStride + (size_t)m0 * K;
    const __half* Bhb = Bh + (size_t)bz * bStride + (size_t)n0 * K;

    const int nK = K / BKC;

    // stage layout: [A 128xBKP][B 128xBKP] fp16
    auto load_stage = [&](int s, int c) {
        char* st = smem + s * STAGE_BYTES;
        const int k0 = c * BKC;
#pragma unroll
        for (int i = 0; i < 2; i++) {
            int job = tid + i * NTH;          // 512 jobs: 128 rows x 4 segs
            int r = job >> 2, seg = job & 3;
            size_t goff = (size_t)r * K + k0 + seg * 8;
            uint32_t soff = (uint32_t)r * (BKP * 2) + seg * 16;
            cp_async16(st + soff,           Ahb + goff);
            cp_async16(st + A_BYTES + soff, Bhb + goff);
        }
    };

    wmma::fragment<wmma::accumulator, 16, 16, 16, float> acc[2][4];
#pragma unroll
    for (int i = 0; i < 2; i++)
#pragma unroll
        for (int j = 0; j < 4; j++) wmma::fill_fragment(acc[i][j], 0.0f);

#pragma unroll
    for (int s = 0; s < NSTAGE; s++) { load_stage(s, s); cp_commit(); }

    const int wm = (wid & 3) * 32;            // 4 m-warps (warp rows 32)
    const int wn = (wid >> 2) * 64;           // 2 n-warps (warp cols 64)

    for (int c = 0; c < nK; c++) {
        cp_wait_group<NSTAGE - 1>();
        __syncthreads();

        const char* st = smem + (c % NSTAGE) * STAGE_BYTES;
        const __half* As = (const __half*)st;
        const __half* Bs = (const __half*)(st + A_BYTES);

#pragma unroll
        for (int ks = 0; ks < 2; ks++) {
            wmma::fragment<wmma::matrix_a, 16, 16, 16, __half, wmma::row_major> fa[2];
            wmma::fragment<wmma::matrix_b, 16, 16, 16, __half, wmma::col_major> fb[4];
#pragma unroll
            for (int i = 0; i < 2; i++)
                wmma::load_matrix_sync(fa[i], As + (wm + i * 16) * BKP + ks * 16, BKP);
#pragma unroll
            for (int j = 0; j < 4; j++)
                wmma::load_matrix_sync(fb[j], Bs + (wn + j * 16) * BKP + ks * 16, BKP);
#pragma unroll
            for (int i = 0; i < 2; i++)
#pragma unroll
                for (int j = 0; j < 4; j++)
                    wmma::mma_sync(acc[i][j], fa[i], fb[j], acc[i][j]);
        }
        __syncthreads();
        if (c + NSTAGE < nK) load_stage(c % NSTAGE, c + NSTAGE);
        cp_commit();
    }
    cp_wait_group<0>();
    __syncthreads();

    // two-pass epilogue: 64 rows at a time through 32KB smem staging
    float* Cs = (float*)smem;
#pragma unroll
    for (int pass = 0; pass < 2; pass++) {
        int rbase = pass * 64;
        if (wm >= rbase && wm < rbase + 64) {
#pragma unroll
            for (int i = 0; i < 2; i++)
#pragma unroll
                for (int j = 0; j < 4; j++)
                    wmma::store_matrix_sync(
                        Cs + (wm - rbase + i * 16) * 128 + wn + j * 16,
                        acc[i][j], 128, wmma::mem_row_major);
        }
        __syncthreads();

#pragma unroll
        for (int it = 0; it < 8; it++) {
            int g = tid + it * NTH;           // 2048 float4 groups (64x128)
            int r = g >> 5, c4 = (g & 31) * 4;
            float4 v = *reinterpret_cast<const float4*>(Cs + r * 128 + c4);
            float o0 = v.x * alpha, o1 = v.y * alpha;
            float o2 = v.z * alpha, o3 = v.w * alpha;
            if (bias) {
                o0 += bias[n0 + c4 + 0];
                o1 += bias[n0 + c4 + 1];
                o2 += bias[n0 + c4 + 2];
                o3 += bias[n0 + c4 + 3];
            }
            int grow = m0 + rbase + r;
            if (outF) {
                float4 w = {o0, o1, o2, o3};
                *reinterpret_cast<float4*>(outF + (size_t)bz * cStride
                    + (size_t)grow * ldC + n0 + c4) = w;
            }
            if (outH) {
                uint2 H;
                H.x = pack_h2(o0, o1);
                H.y = pack_h2(o2, o3);
                size_t e = (size_t)bz * pStride + (size_t)grow * ldP + n0 + c4;
                *reinterpret_cast<uint2*>((char*)outH + e * 2) = H;
            }
        }
        __syncthreads();
    }
}

// ---------------------------------------------------------------------------
extern "C" void kernel_launch(void* const* d_in, const int* in_sizes, int n_in,
                              void* d_out, int out_size)
{
    const float* query = (const float*)d_in[0];
    const float* key   = (const float*)d_in[1];
    const float* value = (const float*)d_in[2];
    const float* Wq    = (const float*)d_in[3];
    const float* bq    = (const float*)d_in[4];
    const float* Wk    = (const float*)d_in[5];
    const float* bk    = (const float*)d_in[6];
    const float* Wv    = (const float*)d_in[7];
    const float* bv    = (const float*)d_in[8];
    float* out = (float*)d_out;

    cudaFuncSetAttribute(tc_gemm, cudaFuncAttributeMaxDynamicSharedMemorySize,
                         GEMM_SMEM);

    __half *xq, *xk, *xv, *wq, *wk, *wv, *Q, *K, *Vt, *S;
    float *Vf, *Sf;
    cudaGetSymbolAddress((void**)&xq, g_xq);
    cudaGetSymbolAddress((void**)&xk, g_xk);
    cudaGetSymbolAddress((void**)&xv, g_xv);
    cudaGetSymbolAddress((void**)&wq, g_wq);
    cudaGetSymbolAddress((void**)&wk, g_wk);
    cudaGetSymbolAddress((void**)&wv, g_wv);
    cudaGetSymbolAddress((void**)&Q, g_Q);
    cudaGetSymbolAddress((void**)&K, g_K);
    cudaGetSymbolAddress((void**)&Vf, g_Vf);
    cudaGetSymbolAddress((void**)&Vt, g_Vt);
    cudaGetSymbolAddress((void**)&Sf, g_Sf);
    cudaGetSymbolAddress((void**)&S, g_S);

    // launch #1: fused packing
    PackJob jq = {query, xq, Wq, wq};
    PackJob jk = {key,   xk, Wk, wk};
    PackJob jv = {value, xv, Wv, wv};
    pack_all<<<dim3(4608, 3), 256>>>(jq, jk, jv);

    // launches #2-4: projections [8192,1024] x W^T + b  (tiles 128x128)
    dim3 gp(8, 64, 1);
    tc_gemm<<<gp, NTH, GEMM_SMEM>>>(xq, wq, CH, 0, 0, bq, 1.0f,
                                    nullptr, 0, 0, Q, CH, 0);
    tc_gemm<<<gp, NTH, GEMM_SMEM>>>(xk, wk, CH, 0, 0, bk, 1.0f,
                                    nullptr, 0, 0, K, CH, 0);
    tc_gemm<<<gp, NTH, GEMM_SMEM>>>(xv, wv, CH, 0, 0, bv, 1.0f,
                                    Vf, CH, 0, nullptr, 0, 0);

    // launch #5: V -> V^T fp16
    transpose_pack<<<dim3(32, 8, 4), 256>>>(Vf, Vt);

    // launch #6 (ncu capture target): scores = Q K^T / 32, per batch
    dim3 gs(16, 16, 4);
    tc_gemm<<<gs, NTH, GEMM_SMEM>>>(Q, K, CH,
                                    (size_t)SEQ * CH, (size_t)SEQ * CH,
                                    nullptr, 1.0f / 32.0f,
                                    Sf, SEQ, (size_t)SEQ * SEQ,
                                    nullptr, 0, 0);

    // launch #7: softmax + fp16 pack
    softmax_pack<<<BATCH * SEQ, 256>>>(Sf, S);

    // launch #8: out = attn @ V, per batch
    dim3 go(8, 16, 4);
    tc_gemm<<<go, NTH, GEMM_SMEM>>>(S, Vt, SEQ,
                                    (size_t)SEQ * SEQ, (size_t)CH * SEQ,
                                    nullptr, 1.0f,
                                    out, CH, (size_t)SEQ * CH,
                                    nullptr, 0, 0);
}

// round 14
// speedup vs baseline: 5.3142x; 1.1692x over previous
#include <cuda_runtime.h>
#include <cuda_fp16.h>
#include <mma.h>
#include <cstdint>
#include <cstddef>

using namespace nvcuda;

#define BATCH 4
#define SEQ   2048
#define CH    1024

// GEMM tiling: CTA 128x128, 8 warps (4m x 2n), warp 32x64, 256 threads,
// 2 CTAs/SM. Single-fp16 operands. BKC=64, double-buffered (NSTAGE=2).
#define NTH 256
#define BKC 64                        // k per stage
#define BKP 72                        // padded smem ld (elems) -> 144B rows
#define A_BYTES (128 * BKP * 2)       // 18432 B
#define B_BYTES (128 * BKP * 2)       // 18432 B
#define STAGE_BYTES (A_BYTES + B_BYTES)       // 36864 B
#define NSTAGE 2
#define GEMM_SMEM (NSTAGE * STAGE_BYTES)      // 73728 B (x2 CTAs = 147456)

// ---------------------------------------------------------------------------
// helpers
// ---------------------------------------------------------------------------
__device__ __forceinline__ uint32_t smem_u32(const void* p) {
    uint32_t a;
    asm("{ .reg .u64 t; cvta.to.shared.u64 t, %1; cvt.u32.u64 %0, t; }"
        : "=r"(a) : "l"(p));
    return a;
}

__device__ __forceinline__ void cp_async16(void* dst, const void* src) {
    uint32_t d = smem_u32(dst);
    asm volatile("cp.async.cg.shared.global [%0], [%1], 16;"
                 :: "r"(d), "l"(src) : "memory");
}
__device__ __forceinline__ void cp_commit() {
    asm volatile("cp.async.commit_group;" ::: "memory");
}
template <int N>
__device__ __forceinline__ void cp_wait_group() {
    asm volatile("cp.async.wait_group %0;" :: "n"(N) : "memory");
}

// fp32 pair -> fp16x2 word
__device__ __forceinline__ uint32_t pack_h2(float a, float b) {
    __half2 h = __floats2half2_rn(a, b);
    return *reinterpret_cast<uint32_t*>(&h);
}

// ---------------------------------------------------------------------------
// scratch
// ---------------------------------------------------------------------------
#define NXE ((size_t)BATCH * SEQ * CH)
#define NWE ((size_t)CH * CH)
#define NSE ((size_t)BATCH * SEQ * SEQ)

__device__ __align__(1024) __half g_xq[NXE], g_xk[NXE], g_xv[NXE];
__device__ __align__(1024) __half g_wq[NWE], g_wk[NWE], g_wv[NWE];
__device__ __align__(1024) __half g_Q[NXE],  g_K[NXE];
__device__ __align__(1024) float  g_Vf[NXE];
__device__ __align__(1024) __half g_Vt[NXE];
__device__ __align__(1024) float  g_Sf[NSE];
__device__ __align__(1024) __half g_S[NSE];

// ---------------------------------------------------------------------------
// fused packing: 3 inputs (4096 blocks) + 3 weights (512 blocks), single fp16
// ---------------------------------------------------------------------------
struct PackJob {
    const float* srcX;  __half* xh;
    const float* srcW;  __half* wh;
};

__global__ void __launch_bounds__(256)
pack_all(PackJob j0, PackJob j1, PackJob j2)
{
    const PackJob& j = (blockIdx.y == 0) ? j0 : (blockIdx.y == 1) ? j1 : j2;
    const float* src;
    __half* dst;
    size_t base;
    if (blockIdx.x < 4096) {
        src = j.srcX; dst = j.xh;
        base = ((size_t)blockIdx.x * 256 + threadIdx.x) * 8;
    } else {
        src = j.srcW; dst = j.wh;
        base = ((size_t)(blockIdx.x - 4096) * 256 + threadIdx.x) * 8;
    }
    float4 f0 = *reinterpret_cast<const float4*>(src + base);
    float4 f1 = *reinterpret_cast<const float4*>(src + base + 4);
    uint4 H;
    H.x = pack_h2(f0.x, f0.y);
    H.y = pack_h2(f0.z, f0.w);
    H.z = pack_h2(f1.x, f1.y);
    H.w = pack_h2(f1.z, f1.w);
    *reinterpret_cast<uint4*>((char*)dst + base * 2) = H;
}

// ---------------------------------------------------------------------------
// V fp32 [B][S][C] -> V^T fp16 [B][C][S]
// ---------------------------------------------------------------------------
__global__ void __launch_bounds__(256)
transpose_pack(const float* __restrict__ V, __half* __restrict__ Dh)
{
    __shared__ float sb[64 * 129];
    int kc = blockIdx.x, dBlk = blockIdx.y, b = blockIdx.z;
    int seq0 = kc * 64, d0 = dBlk * 128;
    int t = threadIdx.x;
#pragma unroll
    for (int i = 0; i < 8; i++) {
        int idx = t + i * 256;
        int s = idx >> 5, d4 = (idx & 31) * 4;
        float4 v = *reinterpret_cast<const float4*>(
            V + ((size_t)b * SEQ + seq0 + s) * CH + d0 + d4);
        sb[s * 129 + d4 + 0] = v.x;
        sb[s * 129 + d4 + 1] = v.y;
        sb[s * 129 + d4 + 2] = v.z;
        sb[s * 129 + d4 + 3] = v.w;
    }
    __syncthreads();
#pragma unroll
    for (int i = 0; i < 4; i++) {
        int idx = t + i * 256;
        int d = idx >> 3, s8 = (idx & 7) * 8;
        uint4 H;
        H.x = pack_h2(sb[(s8 + 0) * 129 + d], sb[(s8 + 1) * 129 + d]);
        H.y = pack_h2(sb[(s8 + 2) * 129 + d], sb[(s8 + 3) * 129 + d]);
        H.z = pack_h2(sb[(s8 + 4) * 129 + d], sb[(s8 + 5) * 129 + d]);
        H.w = pack_h2(sb[(s8 + 6) * 129 + d], sb[(s8 + 7) * 129 + d]);
        size_t e = ((size_t)b * CH + d0 + d) * SEQ + seq0 + s8;
        *reinterpret_cast<uint4*>((char*)Dh + e * 2) = H;
    }
}

// ---------------------------------------------------------------------------
// softmax over rows of S fp32 [B*S][2048] -> single fp16 row-major
// ---------------------------------------------------------------------------
__global__ void __launch_bounds__(256)
softmax_pack(const float* __restrict__ S, __half* __restrict__ Dh)
{
    __shared__ float red[32];
    int rowG = blockIdx.x, t = threadIdx.x;
    const float* row = S + (size_t)rowG * SEQ;
    float4 a = *reinterpret_cast<const float4*>(row + t * 8);
    float4 b2 = *reinterpret_cast<const float4*>(row + t * 8 + 4);
    float v[8] = {a.x, a.y, a.z, a.w, b2.x, b2.y, b2.z, b2.w};

    float m = v[0];
#pragma unroll
    for (int i = 1; i < 8; i++) m = fmaxf(m, v[i]);
#pragma unroll
    for (int o = 16; o > 0; o >>= 1)
        m = fmaxf(m, __shfl_xor_sync(0xffffffffu, m, o));
    if ((t & 31) == 0) red[t >> 5] = m;
    __syncthreads();
    if (t < 32) {
        float x = (t < 8) ? red[t] : -3.4e38f;
#pragma unroll
        for (int o = 4; o > 0; o >>= 1) x = fmaxf(x, __shfl_xor_sync(0xffffffffu, x, o));
        if (t == 0) red[0] = x;
    }
    __syncthreads();
    m = red[0];
    __syncthreads();

    float sum = 0.0f;
#pragma unroll
    for (int i = 0; i < 8; i++) { v[i] = __expf(v[i] - m); sum += v[i]; }
#pragma unroll
    for (int o = 16; o > 0; o >>= 1) sum += __shfl_xor_sync(0xffffffffu, sum, o);
    if ((t & 31) == 0) red[t >> 5] = sum;
    __syncthreads();
    if (t < 32) {
        float x = (t < 8) ? red[t] : 0.0f;
#pragma unroll
        for (int o = 4; o > 0; o >>= 1) x += __shfl_xor_sync(0xffffffffu, x, o);
        if (t == 0) red[0] = x;
    }
    __syncthreads();
    float inv = 1.0f / red[0];

    uint4 H;
    H.x = pack_h2(v[0] * inv, v[1] * inv);
    H.y = pack_h2(v[2] * inv, v[3] * inv);
    H.z = pack_h2(v[4] * inv, v[5] * inv);
    H.w = pack_h2(v[6] * inv, v[7] * inv);
    size_t e = (size_t)rowG * SEQ + t * 8;
    *reinterpret_cast<uint4*>((char*)Dh + e * 2) = H;
}

// ---------------------------------------------------------------------------
// shared GEMM core: WMMA fp16 NT, one 128x128 CTA tile, BKC=64, NSTAGE=2.
// ---------------------------------------------------------------------------
__device__ __forceinline__ void gemm_core(
    char* smem,
    const __half* __restrict__ Ahb, const __half* __restrict__ Bhb,
    int K, const float* __restrict__ bias, float alpha,
    float* __restrict__ outF, int ldC,
    __half* __restrict__ outH, int ldP,
    int m0, int n0)
{
    const int tid = threadIdx.x;
    const int wid = tid >> 5;
    const int nK = K / BKC;

    // stage: [A 128xBKP][B 128xBKP] fp16; 1024 jobs per array (128 rows x 8 segs)
    auto load_stage = [&](int s, int c) {
        char* st = smem + s * STAGE_BYTES;
        const int k0 = c * BKC;
#pragma unroll
        for (int i = 0; i < 4; i++) {
            int job = tid + i * NTH;
            int r = job >> 3, seg = job & 7;
            size_t goff = (size_t)r * K + k0 + seg * 8;
            uint32_t soff = (uint32_t)r * (BKP * 2) + seg * 16;
            cp_async16(st + soff,           Ahb + goff);
            cp_async16(st + A_BYTES + soff, Bhb + goff);
        }
    };

    wmma::fragment<wmma::accumulator, 16, 16, 16, float> acc[2][4];
#pragma unroll
    for (int i = 0; i < 2; i++)
#pragma unroll
        for (int j = 0; j < 4; j++) wmma::fill_fragment(acc[i][j], 0.0f);

    load_stage(0, 0); cp_commit();
    load_stage(1, 1); cp_commit();

    const int wm = (wid & 3) * 32;            // 4 m-warps
    const int wn = (wid >> 2) * 64;           // 2 n-warps

    for (int c = 0; c < nK; c++) {
        cp_wait_group<NSTAGE - 1>();
        __syncthreads();

        const char* st = smem + (c & 1) * STAGE_BYTES;
        const __half* As = (const __half*)st;
        const __half* Bs = (const __half*)(st + A_BYTES);

#pragma unroll
        for (int ks = 0; ks < 4; ks++) {
            wmma::fragment<wmma::matrix_a, 16, 16, 16, __half, wmma::row_major> fa[2];
            wmma::fragment<wmma::matrix_b, 16, 16, 16, __half, wmma::col_major> fb[4];
#pragma unroll
            for (int i = 0; i < 2; i++)
                wmma::load_matrix_sync(fa[i], As + (wm + i * 16) * BKP + ks * 16, BKP);
#pragma unroll
            for (int j = 0; j < 4; j++)
                wmma::load_matrix_sync(fb[j], Bs + (wn + j * 16) * BKP + ks * 16, BKP);
#pragma unroll
            for (int i = 0; i < 2; i++)
#pragma unroll
                for (int j = 0; j < 4; j++)
                    wmma::mma_sync(acc[i][j], fa[i], fb[j], acc[i][j]);
        }
        __syncthreads();
        if (c + NSTAGE < nK) load_stage(c & 1, c + NSTAGE);
        cp_commit();
    }
    cp_wait_group<0>();
    __syncthreads();

    // two-pass epilogue: 64 rows at a time through 32KB smem staging
    float* Cs = (float*)smem;
#pragma unroll
    for (int pass = 0; pass < 2; pass++) {
        int rbase = pass * 64;
        if (wm >= rbase && wm < rbase + 64) {
#pragma unroll
            for (int i = 0; i < 2; i++)
#pragma unroll
                for (int j = 0; j < 4; j++)
                    wmma::store_matrix_sync(
                        Cs + (wm - rbase + i * 16) * 128 + wn + j * 16,
                        acc[i][j], 128, wmma::mem_row_major);
        }
        __syncthreads();

#pragma unroll
        for (int it = 0; it < 8; it++) {
            int g = tid + it * NTH;           // 2048 float4 groups (64x128)
            int r = g >> 5, c4 = (g & 31) * 4;
            float4 v = *reinterpret_cast<const float4*>(Cs + r * 128 + c4);
            float o0 = v.x * alpha, o1 = v.y * alpha;
            float o2 = v.z * alpha, o3 = v.w * alpha;
            if (bias) {
                o0 += bias[n0 + c4 + 0];
                o1 += bias[n0 + c4 + 1];
                o2 += bias[n0 + c4 + 2];
                o3 += bias[n0 + c4 + 3];
            }
            int grow = m0 + rbase + r;
            if (outF) {
                float4 w = {o0, o1, o2, o3};
                *reinterpret_cast<float4*>(outF + (size_t)grow * ldC + n0 + c4) = w;
            }
            if (outH) {
                uint2 H;
                H.x = pack_h2(o0, o1);
                H.y = pack_h2(o2, o3);
                size_t e = (size_t)grow * ldP + n0 + c4;
                *reinterpret_cast<uint2*>((char*)outH + e * 2) = H;
            }
        }
        __syncthreads();
    }
}

// batched GEMM (z = batch index)
__global__ void __launch_bounds__(NTH, 2)
tc_gemm(const __half* __restrict__ Ah, const __half* __restrict__ Bh,
        int K, size_t aStride, size_t bStride,
        const float* __restrict__ bias, float alpha,
        float* __restrict__ outF, int ldC, size_t cStride,
        __half* __restrict__ outH, int ldP, size_t pStride)
{
    extern __shared__ char smem[];
    const int bz = blockIdx.z;
    const int m0 = blockIdx.y * 128, n0 = blockIdx.x * 128;
    gemm_core(smem,
              Ah + (size_t)bz * aStride + (size_t)m0 * K,
              Bh + (size_t)bz * bStride + (size_t)n0 * K,
              K, bias, alpha,
              outF ? outF + (size_t)bz * cStride : nullptr, ldC,
              outH ? outH + (size_t)bz * pStride : nullptr, ldP,
              m0, n0);
}

// fused projections: z = {0:Q, 1:K, 2:V}
struct ProjSet {
    const __half *a, *b;
    const float* bias;
    float* outF;
    __half* outH;
};

__global__ void __launch_bounds__(NTH, 2)
proj_gemm(ProjSet p0, ProjSet p1, ProjSet p2)
{
    extern __shared__ char smem[];
    const ProjSet& p = (blockIdx.z == 0) ? p0 : (blockIdx.z == 1) ? p1 : p2;
    const int m0 = blockIdx.y * 128, n0 = blockIdx.x * 128;
    gemm_core(smem,
              p.a + (size_t)m0 * CH,
              p.b + (size_t)n0 * CH,
              CH, p.bias, 1.0f,
              p.outF, CH, p.outH, CH,
              m0, n0);
}

// ---------------------------------------------------------------------------
extern "C" void kernel_launch(void* const* d_in, const int* in_sizes, int n_in,
                              void* d_out, int out_size)
{
    const float* query = (const float*)d_in[0];
    const float* key   = (const float*)d_in[1];
    const float* value = (const float*)d_in[2];
    const float* Wq    = (const float*)d_in[3];
    const float* bq    = (const float*)d_in[4];
    const float* Wk    = (const float*)d_in[5];
    const float* bk    = (const float*)d_in[6];
    const float* Wv    = (const float*)d_in[7];
    const float* bv    = (const float*)d_in[8];
    float* out = (float*)d_out;

    cudaFuncSetAttribute(tc_gemm, cudaFuncAttributeMaxDynamicSharedMemorySize,
                         GEMM_SMEM);
    cudaFuncSetAttribute(proj_gemm, cudaFuncAttributeMaxDynamicSharedMemorySize,
                         GEMM_SMEM);

    __half *xq, *xk, *xv, *wq, *wk, *wv, *Q, *K, *Vt, *S;
    float *Vf, *Sf;
    cudaGetSymbolAddress((void**)&xq, g_xq);
    cudaGetSymbolAddress((void**)&xk, g_xk);
    cudaGetSymbolAddress((void**)&xv, g_xv);
    cudaGetSymbolAddress((void**)&wq, g_wq);
    cudaGetSymbolAddress((void**)&wk, g_wk);
    cudaGetSymbolAddress((void**)&wv, g_wv);
    cudaGetSymbolAddress((void**)&Q, g_Q);
    cudaGetSymbolAddress((void**)&K, g_K);
    cudaGetSymbolAddress((void**)&Vf, g_Vf);
    cudaGetSymbolAddress((void**)&Vt, g_Vt);
    cudaGetSymbolAddress((void**)&Sf, g_Sf);
    cudaGetSymbolAddress((void**)&S, g_S);

    // launch #1: fused packing
    PackJob jq = {query, xq, Wq, wq};
    PackJob jk = {key,   xk, Wk, wk};
    PackJob jv = {value, xv, Wv, wv};
    pack_all<<<dim3(4608, 3), 256>>>(jq, jk, jv);

    // launch #2: fused Q/K/V projections (1536 CTAs)
    ProjSet pQ = {xq, wq, bq, nullptr, Q};
    ProjSet pK = {xk, wk, bk, nullptr, K};
    ProjSet pV = {xv, wv, bv, Vf, nullptr};
    proj_gemm<<<dim3(8, 64, 3), NTH, GEMM_SMEM>>>(pQ, pK, pV);

    // launch #3: V -> V^T fp16
    transpose_pack<<<dim3(32, 8, 4), 256>>>(Vf, Vt);

    // launch #4: scores = Q K^T / 32, per batch
    dim3 gs(16, 16, 4);
    tc_gemm<<<gs, NTH, GEMM_SMEM>>>(Q, K, CH,
                                    (size_t)SEQ * CH, (size_t)SEQ * CH,
                                    nullptr, 1.0f / 32.0f,
                                    Sf, SEQ, (size_t)SEQ * SEQ,
                                    nullptr, 0, 0);

    // launch #5: softmax + fp16 pack
    softmax_pack<<<BATCH * SEQ, 256>>>(Sf, S);

    // launch #6: out = attn @ V, per batch
    dim3 go(8, 16, 4);
    tc_gemm<<<go, NTH, GEMM_SMEM>>>(S, Vt, SEQ,
                                    (size_t)SEQ * SEQ, (size_t)CH * SEQ,
                                    nullptr, 1.0f,
                                    out, CH, (size_t)SEQ * CH,
                                    nullptr, 0, 0);
}

// round 15
// speedup vs baseline: 5.4112x; 1.0183x over previous
#include <cuda_runtime.h>
#include <cuda_fp16.h>
#include <mma.h>
#include <cstdint>
#include <cstddef>

using namespace nvcuda;

#define BATCH 4
#define SEQ   2048
#define CH    1024

// GEMM tiling: CTA 128x128, 4 warps (2m x 2n), warp 64x64, 128 threads,
// 2 CTAs/SM. Single-fp16 operands. BKC=64, NSTAGE=3.
#define NTH 128
#define BKC 64                        // k per stage
#define BKP 72                        // padded smem ld (elems) -> 144B rows
#define A_BYTES (128 * BKP * 2)       // 18432 B
#define B_BYTES (128 * BKP * 2)       // 18432 B
#define STAGE_BYTES (A_BYTES + B_BYTES)       // 36864 B
#define NSTAGE 3
#define GEMM_SMEM (NSTAGE * STAGE_BYTES)      // 110592 B (x2 CTAs = 221184)

// ---------------------------------------------------------------------------
// helpers
// ---------------------------------------------------------------------------
__device__ __forceinline__ uint32_t smem_u32(const void* p) {
    uint32_t a;
    asm("{ .reg .u64 t; cvta.to.shared.u64 t, %1; cvt.u32.u64 %0, t; }"
        : "=r"(a) : "l"(p));
    return a;
}

__device__ __forceinline__ void cp_async16(void* dst, const void* src) {
    uint32_t d = smem_u32(dst);
    asm volatile("cp.async.cg.shared.global [%0], [%1], 16;"
                 :: "r"(d), "l"(src) : "memory");
}
__device__ __forceinline__ void cp_commit() {
    asm volatile("cp.async.commit_group;" ::: "memory");
}
template <int N>
__device__ __forceinline__ void cp_wait_group() {
    asm volatile("cp.async.wait_group %0;" :: "n"(N) : "memory");
}

// fp32 pair -> fp16x2 word
__device__ __forceinline__ uint32_t pack_h2(float a, float b) {
    __half2 h = __floats2half2_rn(a, b);
    return *reinterpret_cast<uint32_t*>(&h);
}

// ---------------------------------------------------------------------------
// scratch
// ---------------------------------------------------------------------------
#define NXE ((size_t)BATCH * SEQ * CH)
#define NWE ((size_t)CH * CH)
#define NSE ((size_t)BATCH * SEQ * SEQ)

__device__ __align__(1024) __half g_xq[NXE], g_xk[NXE], g_xv[NXE];
__device__ __align__(1024) __half g_wq[NWE], g_wk[NWE], g_wv[NWE];
__device__ __align__(1024) __half g_Q[NXE],  g_K[NXE];
__device__ __align__(1024) float  g_Vf[NXE];
__device__ __align__(1024) __half g_Vt[NXE];
__device__ __align__(1024) float  g_Sf[NSE];
__device__ __align__(1024) __half g_S[NSE];

// ---------------------------------------------------------------------------
// fused packing: 3 inputs (4096 blocks) + 3 weights (512 blocks), single fp16
// ---------------------------------------------------------------------------
struct PackJob {
    const float* srcX;  __half* xh;
    const float* srcW;  __half* wh;
};

__global__ void __launch_bounds__(256)
pack_all(PackJob j0, PackJob j1, PackJob j2)
{
    const PackJob& j = (blockIdx.y == 0) ? j0 : (blockIdx.y == 1) ? j1 : j2;
    const float* src;
    __half* dst;
    size_t base;
    if (blockIdx.x < 4096) {
        src = j.srcX; dst = j.xh;
        base = ((size_t)blockIdx.x * 256 + threadIdx.x) * 8;
    } else {
        src = j.srcW; dst = j.wh;
        base = ((size_t)(blockIdx.x - 4096) * 256 + threadIdx.x) * 8;
    }
    float4 f0 = *reinterpret_cast<const float4*>(src + base);
    float4 f1 = *reinterpret_cast<const float4*>(src + base + 4);
    uint4 H;
    H.x = pack_h2(f0.x, f0.y);
    H.y = pack_h2(f0.z, f0.w);
    H.z = pack_h2(f1.x, f1.y);
    H.w = pack_h2(f1.z, f1.w);
    *reinterpret_cast<uint4*>((char*)dst + base * 2) = H;
}

// ---------------------------------------------------------------------------
// V fp32 [B][S][C] -> V^T fp16 [B][C][S]
// ---------------------------------------------------------------------------
__global__ void __launch_bounds__(256)
transpose_pack(const float* __restrict__ V, __half* __restrict__ Dh)
{
    __shared__ float sb[64 * 129];
    int kc = blockIdx.x, dBlk = blockIdx.y, b = blockIdx.z;
    int seq0 = kc * 64, d0 = dBlk * 128;
    int t = threadIdx.x;
#pragma unroll
    for (int i = 0; i < 8; i++) {
        int idx = t + i * 256;
        int s = idx >> 5, d4 = (idx & 31) * 4;
        float4 v = *reinterpret_cast<const float4*>(
            V + ((size_t)b * SEQ + seq0 + s) * CH + d0 + d4);
        sb[s * 129 + d4 + 0] = v.x;
        sb[s * 129 + d4 + 1] = v.y;
        sb[s * 129 + d4 + 2] = v.z;
        sb[s * 129 + d4 + 3] = v.w;
    }
    __syncthreads();
#pragma unroll
    for (int i = 0; i < 4; i++) {
        int idx = t + i * 256;
        int d = idx >> 3, s8 = (idx & 7) * 8;
        uint4 H;
        H.x = pack_h2(sb[(s8 + 0) * 129 + d], sb[(s8 + 1) * 129 + d]);
        H.y = pack_h2(sb[(s8 + 2) * 129 + d], sb[(s8 + 3) * 129 + d]);
        H.z = pack_h2(sb[(s8 + 4) * 129 + d], sb[(s8 + 5) * 129 + d]);
        H.w = pack_h2(sb[(s8 + 6) * 129 + d], sb[(s8 + 7) * 129 + d]);
        size_t e = ((size_t)b * CH + d0 + d) * SEQ + seq0 + s8;
        *reinterpret_cast<uint4*>((char*)Dh + e * 2) = H;
    }
}

// ---------------------------------------------------------------------------
// softmax over rows of S fp32 [B*S][2048] -> single fp16 row-major
// ---------------------------------------------------------------------------
__global__ void __launch_bounds__(256)
softmax_pack(const float* __restrict__ S, __half* __restrict__ Dh)
{
    __shared__ float red[32];
    int rowG = blockIdx.x, t = threadIdx.x;
    const float* row = S + (size_t)rowG * SEQ;
    float4 a = *reinterpret_cast<const float4*>(row + t * 8);
    float4 b2 = *reinterpret_cast<const float4*>(row + t * 8 + 4);
    float v[8] = {a.x, a.y, a.z, a.w, b2.x, b2.y, b2.z, b2.w};

    float m = v[0];
#pragma unroll
    for (int i = 1; i < 8; i++) m = fmaxf(m, v[i]);
#pragma unroll
    for (int o = 16; o > 0; o >>= 1)
        m = fmaxf(m, __shfl_xor_sync(0xffffffffu, m, o));
    if ((t & 31) == 0) red[t >> 5] = m;
    __syncthreads();
    if (t < 32) {
        float x = (t < 8) ? red[t] : -3.4e38f;
#pragma unroll
        for (int o = 4; o > 0; o >>= 1) x = fmaxf(x, __shfl_xor_sync(0xffffffffu, x, o));
        if (t == 0) red[0] = x;
    }
    __syncthreads();
    m = red[0];
    __syncthreads();

    float sum = 0.0f;
#pragma unroll
    for (int i = 0; i < 8; i++) { v[i] = __expf(v[i] - m); sum += v[i]; }
#pragma unroll
    for (int o = 16; o > 0; o >>= 1) sum += __shfl_xor_sync(0xffffffffu, sum, o);
    if ((t & 31) == 0) red[t >> 5] = sum;
    __syncthreads();
    if (t < 32) {
        float x = (t < 8) ? red[t] : 0.0f;
#pragma unroll
        for (int o = 4; o > 0; o >>= 1) x += __shfl_xor_sync(0xffffffffu, x, o);
        if (t == 0) red[0] = x;
    }
    __syncthreads();
    float inv = 1.0f / red[0];

    uint4 H;
    H.x = pack_h2(v[0] * inv, v[1] * inv);
    H.y = pack_h2(v[2] * inv, v[3] * inv);
    H.z = pack_h2(v[4] * inv, v[5] * inv);
    H.w = pack_h2(v[6] * inv, v[7] * inv);
    size_t e = (size_t)rowG * SEQ + t * 8;
    *reinterpret_cast<uint4*>((char*)Dh + e * 2) = H;
}

// ---------------------------------------------------------------------------
// shared GEMM core: WMMA fp16 NT, one 128x128 CTA tile, 4 warps (64x64 each),
// BKC=64, NSTAGE=3.
// ---------------------------------------------------------------------------
__device__ __forceinline__ void gemm_core(
    char* smem,
    const __half* __restrict__ Ahb, const __half* __restrict__ Bhb,
    int K, const float* __restrict__ bias, float alpha,
    float* __restrict__ outF, int ldC,
    __half* __restrict__ outH, int ldP,
    int m0, int n0)
{
    const int tid = threadIdx.x;
    const int wid = tid >> 5;
    const int nK = K / BKC;

    // stage: [A 128xBKP][B 128xBKP] fp16; 1024 jobs per array (128 rows x 8 segs)
    auto load_stage = [&](int s, int c) {
        char* st = smem + s * STAGE_BYTES;
        const int k0 = c * BKC;
#pragma unroll
        for (int i = 0; i < 8; i++) {
            int job = tid + i * NTH;
            int r = job >> 3, seg = job & 7;
            size_t goff = (size_t)r * K + k0 + seg * 8;
            uint32_t soff = (uint32_t)r * (BKP * 2) + seg * 16;
            cp_async16(st + soff,           Ahb + goff);
            cp_async16(st + A_BYTES + soff, Bhb + goff);
        }
    };

    wmma::fragment<wmma::accumulator, 16, 16, 16, float> acc[4][4];
#pragma unroll
    for (int i = 0; i < 4; i++)
#pragma unroll
        for (int j = 0; j < 4; j++) wmma::fill_fragment(acc[i][j], 0.0f);

#pragma unroll
    for (int s = 0; s < NSTAGE; s++) { load_stage(s, s); cp_commit(); }

    const int wm = (wid & 1) * 64;            // 2 m-warps
    const int wn = (wid >> 1) * 64;           // 2 n-warps

    for (int c = 0; c < nK; c++) {
        cp_wait_group<NSTAGE - 1>();
        __syncthreads();

        const char* st = smem + (c % NSTAGE) * STAGE_BYTES;
        const __half* As = (const __half*)st;
        const __half* Bs = (const __half*)(st + A_BYTES);

#pragma unroll
        for (int ks = 0; ks < 4; ks++) {
            wmma::fragment<wmma::matrix_a, 16, 16, 16, __half, wmma::row_major> fa[4];
#pragma unroll
            for (int i = 0; i < 4; i++)
                wmma::load_matrix_sync(fa[i], As + (wm + i * 16) * BKP + ks * 16, BKP);
#pragma unroll
            for (int j = 0; j < 4; j++) {
                wmma::fragment<wmma::matrix_b, 16, 16, 16, __half, wmma::col_major> fb;
                wmma::load_matrix_sync(fb, Bs + (wn + j * 16) * BKP + ks * 16, BKP);
#pragma unroll
                for (int i = 0; i < 4; i++)
                    wmma::mma_sync(acc[i][j], fa[i], fb, acc[i][j]);
            }
        }
        __syncthreads();
        if (c + NSTAGE < nK) load_stage(c % NSTAGE, c + NSTAGE);
        cp_commit();
    }
    cp_wait_group<0>();
    __syncthreads();

    // epilogue via smem staging (128x128 fp32 = 64KB <= 108KB stage mem)
    float* Cs = (float*)smem;
#pragma unroll
    for (int i = 0; i < 4; i++)
#pragma unroll
        for (int j = 0; j < 4; j++)
            wmma::store_matrix_sync(Cs + (wm + i * 16) * 128 + wn + j * 16,
                                    acc[i][j], 128, wmma::mem_row_major);
    __syncthreads();

#pragma unroll
    for (int it = 0; it < 32; it++) {
        int g = tid + it * NTH;               // 4096 float4 groups (128x128)
        int r = g >> 5, c4 = (g & 31) * 4;
        float4 v = *reinterpret_cast<const float4*>(Cs + r * 128 + c4);
        float o0 = v.x * alpha, o1 = v.y * alpha;
        float o2 = v.z * alpha, o3 = v.w * alpha;
        if (bias) {
            o0 += bias[n0 + c4 + 0];
            o1 += bias[n0 + c4 + 1];
            o2 += bias[n0 + c4 + 2];
            o3 += bias[n0 + c4 + 3];
        }
        int grow = m0 + r;
        if (outF) {
            float4 w = {o0, o1, o2, o3};
            *reinterpret_cast<float4*>(outF + (size_t)grow * ldC + n0 + c4) = w;
        }
        if (outH) {
            uint2 H;
            H.x = pack_h2(o0, o1);
            H.y = pack_h2(o2, o3);
            size_t e = (size_t)grow * ldP + n0 + c4;
            *reinterpret_cast<uint2*>((char*)outH + e * 2) = H;
        }
    }
}

// batched GEMM (z = batch index)
__global__ void __launch_bounds__(NTH, 2)
tc_gemm(const __half* __restrict__ Ah, const __half* __restrict__ Bh,
        int K, size_t aStride, size_t bStride,
        const float* __restrict__ bias, float alpha,
        float* __restrict__ outF, int ldC, size_t cStride,
        __half* __restrict__ outH, int ldP, size_t pStride)
{
    extern __shared__ char smem[];
    const int bz = blockIdx.z;
    const int m0 = blockIdx.y * 128, n0 = blockIdx.x * 128;
    gemm_core(smem,
              Ah + (size_t)bz * aStride + (size_t)m0 * K,
              Bh + (size_t)bz * bStride + (size_t)n0 * K,
              K, bias, alpha,
              outF ? outF + (size_t)bz * cStride : nullptr, ldC,
              outH ? outH + (size_t)bz * pStride : nullptr, ldP,
              m0, n0);
}

// fused projections: z = {0:Q, 1:K, 2:V}
struct ProjSet {
    const __half *a, *b;
    const float* bias;
    float* outF;
    __half* outH;
};

__global__ void __launch_bounds__(NTH, 2)
proj_gemm(ProjSet p0, ProjSet p1, ProjSet p2)
{
    extern __shared__ char smem[];
    const ProjSet& p = (blockIdx.z == 0) ? p0 : (blockIdx.z == 1) ? p1 : p2;
    const int m0 = blockIdx.y * 128, n0 = blockIdx.x * 128;
    gemm_core(smem,
              p.a + (size_t)m0 * CH,
              p.b + (size_t)n0 * CH,
              CH, p.bias, 1.0f,
              p.outF, CH, p.outH, CH,
              m0, n0);
}

// ---------------------------------------------------------------------------
extern "C" void kernel_launch(void* const* d_in, const int* in_sizes, int n_in,
                              void* d_out, int out_size)
{
    const float* query = (const float*)d_in[0];
    const float* key   = (const float*)d_in[1];
    const float* value = (const float*)d_in[2];
    const float* Wq    = (const float*)d_in[3];
    const float* bq    = (const float*)d_in[4];
    const float* Wk    = (const float*)d_in[5];
    const float* bk    = (const float*)d_in[6];
    const float* Wv    = (const float*)d_in[7];
    const float* bv    = (const float*)d_in[8];
    float* out = (float*)d_out;

    cudaFuncSetAttribute(tc_gemm, cudaFuncAttributeMaxDynamicSharedMemorySize,
                         GEMM_SMEM);
    cudaFuncSetAttribute(proj_gemm, cudaFuncAttributeMaxDynamicSharedMemorySize,
                         GEMM_SMEM);

    __half *xq, *xk, *xv, *wq, *wk, *wv, *Q, *K, *Vt, *S;
    float *Vf, *Sf;
    cudaGetSymbolAddress((void**)&xq, g_xq);
    cudaGetSymbolAddress((void**)&xk, g_xk);
    cudaGetSymbolAddress((void**)&xv, g_xv);
    cudaGetSymbolAddress((void**)&wq, g_wq);
    cudaGetSymbolAddress((void**)&wk, g_wk);
    cudaGetSymbolAddress((void**)&wv, g_wv);
    cudaGetSymbolAddress((void**)&Q, g_Q);
    cudaGetSymbolAddress((void**)&K, g_K);
    cudaGetSymbolAddress((void**)&Vf, g_Vf);
    cudaGetSymbolAddress((void**)&Vt, g_Vt);
    cudaGetSymbolAddress((void**)&Sf, g_Sf);
    cudaGetSymbolAddress((void**)&S, g_S);

    // launch #1: fused packing
    PackJob jq = {query, xq, Wq, wq};
    PackJob jk = {key,   xk, Wk, wk};
    PackJob jv = {value, xv, Wv, wv};
    pack_all<<<dim3(4608, 3), 256>>>(jq, jk, jv);

    // launch #2: fused Q/K/V projections (1536 CTAs)
    ProjSet pQ = {xq, wq, bq, nullptr, Q};
    ProjSet pK = {xk, wk, bk, nullptr, K};
    ProjSet pV = {xv, wv, bv, Vf, nullptr};
    proj_gemm<<<dim3(8, 64, 3), NTH, GEMM_SMEM>>>(pQ, pK, pV);

    // launch #3: V -> V^T fp16
    transpose_pack<<<dim3(32, 8, 4), 256>>>(Vf, Vt);

    // launch #4: scores = Q K^T / 32, per batch
    dim3 gs(16, 16, 4);
    tc_gemm<<<gs, NTH, GEMM_SMEM>>>(Q, K, CH,
                                    (size_t)SEQ * CH, (size_t)SEQ * CH,
                                    nullptr, 1.0f / 32.0f,
                                    Sf, SEQ, (size_t)SEQ * SEQ,
                                    nullptr, 0, 0);

    // launch #5: softmax + fp16 pack
    softmax_pack<<<BATCH * SEQ, 256>>>(Sf, S);

    // launch #6: out = attn @ V, per batch
    dim3 go(8, 16, 4);
    tc_gemm<<<go, NTH, GEMM_SMEM>>>(S, Vt, SEQ,
                                    (size_t)SEQ * SEQ, (size_t)CH * SEQ,
                                    nullptr, 1.0f,
                                    out, CH, (size_t)SEQ * CH,
                                    nullptr, 0, 0);
}

// round 16
// speedup vs baseline: 5.5304x; 1.0220x over previous
#include <cuda_runtime.h>
#include <cuda_fp16.h>
#include <mma.h>
#include <cstdint>
#include <cstddef>

using namespace nvcuda;

#define BATCH 4
#define SEQ   2048
#define CH    1024

// GEMM tiling (R15-proven): CTA 128x128, 4 warps (2m x 2n), warp 64x64,
// 128 threads, 2 CTAs/SM. Single-fp16. BKC=64, NSTAGE=3.
#define NTH 128
#define BKC 64
#define BKP 72                        // padded smem ld (elems) -> 144B rows
#define A_BYTES (128 * BKP * 2)       // 18432 B
#define B_BYTES (128 * BKP * 2)       // 18432 B
#define STAGE_BYTES (A_BYTES + B_BYTES)       // 36864 B
#define NSTAGE 3
#define GEMM_SMEM (NSTAGE * STAGE_BYTES)      // 110592 B (x2 CTAs = 221184)

// ---------------------------------------------------------------------------
// helpers
// ---------------------------------------------------------------------------
__device__ __forceinline__ uint32_t smem_u32(const void* p) {
    uint32_t a;
    asm("{ .reg .u64 t; cvta.to.shared.u64 t, %1; cvt.u32.u64 %0, t; }"
        : "=r"(a) : "l"(p));
    return a;
}

__device__ __forceinline__ void cp_async16(void* dst, const void* src) {
    uint32_t d = smem_u32(dst);
    asm volatile("cp.async.cg.shared.global [%0], [%1], 16;"
                 :: "r"(d), "l"(src) : "memory");
}
__device__ __forceinline__ void cp_commit() {
    asm volatile("cp.async.commit_group;" ::: "memory");
}
template <int N>
__device__ __forceinline__ void cp_wait_group() {
    asm volatile("cp.async.wait_group %0;" :: "n"(N) : "memory");
}

__device__ __forceinline__ uint32_t pack_h2(float a, float b) {
    __half2 h = __floats2half2_rn(a, b);
    return *reinterpret_cast<uint32_t*>(&h);
}

// ---------------------------------------------------------------------------
// scratch
// ---------------------------------------------------------------------------
#define NXE ((size_t)BATCH * SEQ * CH)
#define NWE ((size_t)CH * CH)
#define NSE ((size_t)BATCH * SEQ * SEQ)

__device__ __align__(1024) __half g_xq[NXE], g_xk[NXE], g_xv[NXE];
__device__ __align__(1024) __half g_wq[NWE], g_wk[NWE], g_wv[NWE];
__device__ __align__(1024) __half g_Q[NXE],  g_K[NXE];
__device__ __align__(1024) __half g_Vt[NXE];
__device__ __align__(1024) float  g_Sf[NSE];
__device__ __align__(1024) __half g_S[NSE];

// ---------------------------------------------------------------------------
// fused packing: 3 inputs (4096 blocks) + 3 weights (512 blocks), single fp16
// ---------------------------------------------------------------------------
struct PackJob {
    const float* srcX;  __half* xh;
    const float* srcW;  __half* wh;
};

__global__ void __launch_bounds__(256)
pack_all(PackJob j0, PackJob j1, PackJob j2)
{
    const PackJob& j = (blockIdx.y == 0) ? j0 : (blockIdx.y == 1) ? j1 : j2;
    const float* src;
    __half* dst;
    size_t base;
    if (blockIdx.x < 4096) {
        src = j.srcX; dst = j.xh;
        base = ((size_t)blockIdx.x * 256 + threadIdx.x) * 8;
    } else {
        src = j.srcW; dst = j.wh;
        base = ((size_t)(blockIdx.x - 4096) * 256 + threadIdx.x) * 8;
    }
    float4 f0 = *reinterpret_cast<const float4*>(src + base);
    float4 f1 = *reinterpret_cast<const float4*>(src + base + 4);
    uint4 H;
    H.x = pack_h2(f0.x, f0.y);
    H.y = pack_h2(f0.z, f0.w);
    H.z = pack_h2(f1.x, f1.y);
    H.w = pack_h2(f1.z, f1.w);
    *reinterpret_cast<uint4*>((char*)dst + base * 2) = H;
}

// ---------------------------------------------------------------------------
// softmax over rows of S fp32 [B*S][2048] -> single fp16 row-major
// ---------------------------------------------------------------------------
__global__ void __launch_bounds__(256)
softmax_pack(const float* __restrict__ S, __half* __restrict__ Dh)
{
    __shared__ float red[32];
    int rowG = blockIdx.x, t = threadIdx.x;
    const float* row = S + (size_t)rowG * SEQ;
    float4 a = *reinterpret_cast<const float4*>(row + t * 8);
    float4 b2 = *reinterpret_cast<const float4*>(row + t * 8 + 4);
    float v[8] = {a.x, a.y, a.z, a.w, b2.x, b2.y, b2.z, b2.w};

    float m = v[0];
#pragma unroll
    for (int i = 1; i < 8; i++) m = fmaxf(m, v[i]);
#pragma unroll
    for (int o = 16; o > 0; o >>= 1)
        m = fmaxf(m, __shfl_xor_sync(0xffffffffu, m, o));
    if ((t & 31) == 0) red[t >> 5] = m;
    __syncthreads();
    if (t < 32) {
        float x = (t < 8) ? red[t] : -3.4e38f;
#pragma unroll
        for (int o = 4; o > 0; o >>= 1) x = fmaxf(x, __shfl_xor_sync(0xffffffffu, x, o));
        if (t == 0) red[0] = x;
    }
    __syncthreads();
    m = red[0];
    __syncthreads();

    float sum = 0.0f;
#pragma unroll
    for (int i = 0; i < 8; i++) { v[i] = __expf(v[i] - m); sum += v[i]; }
#pragma unroll
    for (int o = 16; o > 0; o >>= 1) sum += __shfl_xor_sync(0xffffffffu, sum, o);
    if ((t & 31) == 0) red[t >> 5] = sum;
    __syncthreads();
    if (t < 32) {
        float x = (t < 8) ? red[t] : 0.0f;
#pragma unroll
        for (int o = 4; o > 0; o >>= 1) x += __shfl_xor_sync(0xffffffffu, x, o);
        if (t == 0) red[0] = x;
    }
    __syncthreads();
    float inv = 1.0f / red[0];

    uint4 H;
    H.x = pack_h2(v[0] * inv, v[1] * inv);
    H.y = pack_h2(v[2] * inv, v[3] * inv);
    H.z = pack_h2(v[4] * inv, v[5] * inv);
    H.w = pack_h2(v[6] * inv, v[7] * inv);
    size_t e = (size_t)rowG * SEQ + t * 8;
    *reinterpret_cast<uint4*>((char*)Dh + e * 2) = H;
}

// ---------------------------------------------------------------------------
// GEMM mainloop (R15-proven): fills acc[4][4] for one 128x128 tile.
// ---------------------------------------------------------------------------
__device__ __forceinline__ void gemm_mainloop(
    char* smem, const __half* __restrict__ Ahb, const __half* __restrict__ Bhb,
    int K, wmma::fragment<wmma::accumulator, 16, 16, 16, float> (&acc)[4][4],
    int wm, int wn)
{
    const int tid = threadIdx.x;
    const int nK = K / BKC;

    auto load_stage = [&](int s, int c) {
        char* st = smem + s * STAGE_BYTES;
        const int k0 = c * BKC;
#pragma unroll
        for (int i = 0; i < 8; i++) {
            int job = tid + i * NTH;
            int r = job >> 3, seg = job & 7;
            size_t goff = (size_t)r * K + k0 + seg * 8;
            uint32_t soff = (uint32_t)r * (BKP * 2) + seg * 16;
            cp_async16(st + soff,           Ahb + goff);
            cp_async16(st + A_BYTES + soff, Bhb + goff);
        }
    };

#pragma unroll
    for (int i = 0; i < 4; i++)
#pragma unroll
        for (int j = 0; j < 4; j++) wmma::fill_fragment(acc[i][j], 0.0f);

#pragma unroll
    for (int s = 0; s < NSTAGE; s++) { load_stage(s, s); cp_commit(); }

    for (int c = 0; c < nK; c++) {
        cp_wait_group<NSTAGE - 1>();
        __syncthreads();

        const char* st = smem + (c % NSTAGE) * STAGE_BYTES;
        const __half* As = (const __half*)st;
        const __half* Bs = (const __half*)(st + A_BYTES);

#pragma unroll
        for (int ks = 0; ks < 4; ks++) {
            wmma::fragment<wmma::matrix_a, 16, 16, 16, __half, wmma::row_major> fa[4];
#pragma unroll
            for (int i = 0; i < 4; i++)
                wmma::load_matrix_sync(fa[i], As + (wm + i * 16) * BKP + ks * 16, BKP);
#pragma unroll
            for (int j = 0; j < 4; j++) {
                wmma::fragment<wmma::matrix_b, 16, 16, 16, __half, wmma::col_major> fb;
                wmma::load_matrix_sync(fb, Bs + (wn + j * 16) * BKP + ks * 16, BKP);
#pragma unroll
                for (int i = 0; i < 4; i++)
                    wmma::mma_sync(acc[i][j], fa[i], fb, acc[i][j]);
            }
        }
        __syncthreads();
        if (c + NSTAGE < nK) load_stage(c % NSTAGE, c + NSTAGE);
        cp_commit();
    }
    cp_wait_group<0>();
    __syncthreads();
}

// ---------------------------------------------------------------------------
// direct-epilogue GEMM (no bias): C = alpha * A B^T, fp32 written straight
// from fragments to global (no smem staging).
// ---------------------------------------------------------------------------
__global__ void __launch_bounds__(NTH, 2)
tc_gemm_direct(const __half* __restrict__ Ah, const __half* __restrict__ Bh,
               int K, size_t aStride, size_t bStride, float alpha,
               float* __restrict__ outF, int ldC, size_t cStride)
{
    extern __shared__ char smem[];
    const int wid = threadIdx.x >> 5;
    const int bz = blockIdx.z;
    const int m0 = blockIdx.y * 128, n0 = blockIdx.x * 128;
    const int wm = (wid & 1) * 64, wn = (wid >> 1) * 64;

    wmma::fragment<wmma::accumulator, 16, 16, 16, float> acc[4][4];
    gemm_mainloop(smem,
                  Ah + (size_t)bz * aStride + (size_t)m0 * K,
                  Bh + (size_t)bz * bStride + (size_t)n0 * K,
                  K, acc, wm, wn);

    float* base = outF + (size_t)bz * cStride;
#pragma unroll
    for (int i = 0; i < 4; i++)
#pragma unroll
        for (int j = 0; j < 4; j++) {
#pragma unroll
            for (int e = 0; e < acc[i][j].num_elements; e++)
                acc[i][j].x[e] *= alpha;
            wmma::store_matrix_sync(
                base + (size_t)(m0 + wm + i * 16) * ldC + n0 + wn + j * 16,
                acc[i][j], ldC, wmma::mem_row_major);
        }
}

// ---------------------------------------------------------------------------
// fused projections: z = {0:Q, 1:K, 2:V}.  Q/K: bias + fp16 row-major out.
// V: bias + fp16 TRANSPOSED out (writes Vt[B][C][S] directly).
// ---------------------------------------------------------------------------
struct ProjSet {
    const __half *a, *b;
    const float* bias;
    __half* outH;
    int transposed;
};

__global__ void __launch_bounds__(NTH, 2)
proj_gemm(ProjSet p0, ProjSet p1, ProjSet p2)
{
    extern __shared__ char smem[];
    const ProjSet& p = (blockIdx.z == 0) ? p0 : (blockIdx.z == 1) ? p1 : p2;
    const int tid = threadIdx.x;
    const int wid = tid >> 5, lane = tid & 31;
    const int m0 = blockIdx.y * 128, n0 = blockIdx.x * 128;
    const int wm = (wid & 1) * 64, wn = (wid >> 1) * 64;

    wmma::fragment<wmma::accumulator, 16, 16, 16, float> acc[4][4];
    gemm_mainloop(smem,
                  p.a + (size_t)m0 * CH,
                  p.b + (size_t)n0 * CH,
                  CH, acc, wm, wn);

    if (!p.transposed) {
        // staged epilogue: bias + fp16 row-major (ld 128)
        float* Cs = (float*)smem;
#pragma unroll
        for (int i = 0; i < 4; i++)
#pragma unroll
            for (int j = 0; j < 4; j++)
                wmma::store_matrix_sync(Cs + (wm + i * 16) * 128 + wn + j * 16,
                                        acc[i][j], 128, wmma::mem_row_major);
        __syncthreads();
#pragma unroll
        for (int it = 0; it < 32; it++) {
            int g = tid + it * NTH;           // 4096 float4 groups
            int r = g >> 5, c4 = (g & 31) * 4;
            float4 v = *reinterpret_cast<const float4*>(Cs + r * 128 + c4);
            float o0 = v.x + p.bias[n0 + c4 + 0];
            float o1 = v.y + p.bias[n0 + c4 + 1];
            float o2 = v.z + p.bias[n0 + c4 + 2];
            float o3 = v.w + p.bias[n0 + c4 + 3];
            uint2 H;
            H.x = pack_h2(o0, o1);
            H.y = pack_h2(o2, o3);
            size_t e = (size_t)(m0 + r) * CH + n0 + c4;
            *reinterpret_cast<uint2*>((char*)p.outH + e * 2) = H;
        }
    } else {
        // V: staged with ld 132 (conflict-reduced column reads), write Vt
        float* Cs = (float*)smem;
#pragma unroll
        for (int i = 0; i < 4; i++)
#pragma unroll
            for (int j = 0; j < 4; j++)
                wmma::store_matrix_sync(Cs + (wm + i * 16) * 132 + wn + j * 16,
                                        acc[i][j], 132, wmma::mem_row_major);
        __syncthreads();

        int b = m0 >> 11;                     // batch
        int s0 = m0 & 2047;                   // seq offset within batch
#pragma unroll
        for (int rr = 0; rr < 32; rr++) {
            int c = wid * 32 + rr;            // local channel 0..127
            float bv = p.bias[n0 + c];
            __half* dst = p.outH + ((size_t)b * CH + n0 + c) * SEQ + s0;
#pragma unroll
            for (int k = 0; k < 4; k++) {
                int s = k * 32 + lane;
                float val = Cs[s * 132 + c] + bv;
                dst[s] = __float2half_rn(val);
            }
        }
    }
}

// ---------------------------------------------------------------------------
extern "C" void kernel_launch(void* const* d_in, const int* in_sizes, int n_in,
                              void* d_out, int out_size)
{
    const float* query = (const float*)d_in[0];
    const float* key   = (const float*)d_in[1];
    const float* value = (const float*)d_in[2];
    const float* Wq    = (const float*)d_in[3];
    const float* bq    = (const float*)d_in[4];
    const float* Wk    = (const float*)d_in[5];
    const float* bk    = (const float*)d_in[6];
    const float* Wv    = (const float*)d_in[7];
    const float* bv    = (const float*)d_in[8];
    float* out = (float*)d_out;

    cudaFuncSetAttribute(tc_gemm_direct, cudaFuncAttributeMaxDynamicSharedMemorySize,
                         GEMM_SMEM);
    cudaFuncSetAttribute(proj_gemm, cudaFuncAttributeMaxDynamicSharedMemorySize,
                         GEMM_SMEM);

    __half *xq, *xk, *xv, *wq, *wk, *wv, *Q, *K, *Vt, *S;
    float *Sf;
    cudaGetSymbolAddress((void**)&xq, g_xq);
    cudaGetSymbolAddress((void**)&xk, g_xk);
    cudaGetSymbolAddress((void**)&xv, g_xv);
    cudaGetSymbolAddress((void**)&wq, g_wq);
    cudaGetSymbolAddress((void**)&wk, g_wk);
    cudaGetSymbolAddress((void**)&wv, g_wv);
    cudaGetSymbolAddress((void**)&Q, g_Q);
    cudaGetSymbolAddress((void**)&K, g_K);
    cudaGetSymbolAddress((void**)&Vt, g_Vt);
    cudaGetSymbolAddress((void**)&Sf, g_Sf);
    cudaGetSymbolAddress((void**)&S, g_S);

    // launch #1: fused packing
    PackJob jq = {query, xq, Wq, wq};
    PackJob jk = {key,   xk, Wk, wk};
    PackJob jv = {value, xv, Wv, wv};
    pack_all<<<dim3(4608, 3), 256>>>(jq, jk, jv);

    // launch #2: fused Q/K/V projections (V writes Vt transposed directly)
    ProjSet pQ = {xq, wq, bq, Q,  0};
    ProjSet pK = {xk, wk, bk, K,  0};
    ProjSet pV = {xv, wv, bv, Vt, 1};
    proj_gemm<<<dim3(8, 64, 3), NTH, GEMM_SMEM>>>(pQ, pK, pV);

    // launch #3: scores = Q K^T / 32, per batch (direct fp32 epilogue)
    dim3 gs(16, 16, 4);
    tc_gemm_direct<<<gs, NTH, GEMM_SMEM>>>(Q, K, CH,
                                           (size_t)SEQ * CH, (size_t)SEQ * CH,
                                           1.0f / 32.0f,
                                           Sf, SEQ, (size_t)SEQ * SEQ);

    // launch #4: softmax + fp16 pack
    softmax_pack<<<BATCH * SEQ, 256>>>(Sf, S);

    // launch #5: out = attn @ V, per batch (direct fp32 epilogue)
    dim3 go(8, 16, 4);
    tc_gemm_direct<<<go, NTH, GEMM_SMEM>>>(S, Vt, SEQ,
                                           (size_t)SEQ * SEQ, (size_t)CH * SEQ,
                                           1.0f,
                                           out, CH, (size_t)SEQ * CH);
}